// round 6
// baseline (speedup 1.0000x reference)
#include <cuda_runtime.h>
#include <math.h>

#define NPTS 16384
#define KNN  16
#define GD   32
#define NCELLS (GD * GD * GD)

// ---------------- scratch (device globals; no allocation allowed) ----------------
__device__ float4 g_pts [NPTS];
__device__ float4 g_spts[NPTS];
__device__ int    g_pcell[NPTS];
__device__ int    g_ssid [NPTS];
__device__ int    g_scell[NPTS];
__device__ int    g_hist [NCELLS];
__device__ int    g_cellstart[NCELLS + 1];
__device__ int    g_cellptr  [NCELLS];
__device__ unsigned g_bbmin[3];
__device__ unsigned g_bbmax[3];
__device__ unsigned g_done;
__device__ float  g_gp[8];     // ox,oy,oz, ix,iy,iz, hmin, hdiag2
__device__ int    g_nbr [NPTS * KNN];
__device__ float  g_qkvs[NPTS * 512];
__device__ float  g_h1 [NPTS * 128];
__device__ float  g_h2 [NPTS * 128];
__device__ float  g_Wp1[64  * 512];
__device__ float  g_Wp2[128 * 512];
__device__ float  g_Wp3[128 * 12];
__device__ float  g_Bp1[512];
__device__ float  g_Bp2[512];
__device__ float  g_Bp3[12];

// monotone float <-> unsigned key
__device__ __forceinline__ unsigned fkey(float f) {
    unsigned u = __float_as_uint(f);
    return (u & 0x80000000u) ? ~u : (u | 0x80000000u);
}
__device__ __forceinline__ float funkey(unsigned u) {
    u = (u & 0x80000000u) ? (u & 0x7fffffffu) : ~u;
    return __uint_as_float(u);
}

// ---------------- bbox over coords; last block computes grid params ----------------
__global__ void bbox_kernel(const float* __restrict__ x) {
    __shared__ float smn[3][8], smx[3][8];
    int tid = threadIdx.x;
    int i = blockIdx.x * 256 + tid;          // 64 blocks x 256 = 16384
    float v[3];
    v[0] = x[i * 64 + 0]; v[1] = x[i * 64 + 1]; v[2] = x[i * 64 + 2];
    float mn[3] = {v[0], v[1], v[2]}, mx[3] = {v[0], v[1], v[2]};
#pragma unroll
    for (int o = 16; o > 0; o >>= 1)
#pragma unroll
        for (int d = 0; d < 3; d++) {
            mn[d] = fminf(mn[d], __shfl_xor_sync(0xffffffffu, mn[d], o));
            mx[d] = fmaxf(mx[d], __shfl_xor_sync(0xffffffffu, mx[d], o));
        }
    int w = tid >> 5, l = tid & 31;
    if (l == 0)
#pragma unroll
        for (int d = 0; d < 3; d++) { smn[d][w] = mn[d]; smx[d][w] = mx[d]; }
    __syncthreads();
    if (tid == 0) {
#pragma unroll
        for (int d = 0; d < 3; d++) {
            float a = smn[d][0], b = smx[d][0];
            for (int ww = 1; ww < 8; ww++) {
                a = fminf(a, smn[d][ww]); b = fmaxf(b, smx[d][ww]);
            }
            atomicMin(&g_bbmin[d], fkey(a));
            atomicMax(&g_bbmax[d], fkey(b));
        }
        __threadfence();
        if (atomicAdd(&g_done, 1u) == 63u) {
            float hmin = 1e30f, hd2 = 0.f;
            for (int d = 0; d < 3; d++) {
                float lo = funkey(atomicAdd(&g_bbmin[d], 0u)) - 1e-4f;
                float hi = funkey(atomicAdd(&g_bbmax[d], 0u)) + 1e-4f;
                float h = (hi - lo) / (float)GD;
                g_gp[d] = lo;
                g_gp[3 + d] = (float)GD / (hi - lo);
                hmin = fminf(hmin, h);
                hd2 += h * h;
            }
            g_gp[6] = hmin;
            g_gp[7] = hd2;                    // hx^2+hy^2+hz^2
        }
    }
}

// ---------------- pack coords + |p|^2, cell assignment, histogram ----------------
__global__ void prep_hist_kernel(const float* __restrict__ x) {
    int i = blockIdx.x * blockDim.x + threadIdx.x;
    if (i >= NPTS) return;
    float a = x[i * 64 + 0], b = x[i * 64 + 1], c = x[i * 64 + 2];
    g_pts[i] = make_float4(a, b, c, a * a + b * b + c * c);
    int cx = min(max((int)((a - g_gp[0]) * g_gp[3]), 0), GD - 1);
    int cy = min(max((int)((b - g_gp[1]) * g_gp[4]), 0), GD - 1);
    int cz = min(max((int)((c - g_gp[2]) * g_gp[5]), 0), GD - 1);
    int cell = (cz << 10) | (cy << 5) | cx;
    g_pcell[i] = cell;
    atomicAdd(&g_hist[cell], 1);
}

// ---------------- single-block scan of 32768 cells + scatter ----------------
__global__ void __launch_bounds__(1024) scan_scatter_kernel() {
    __shared__ int sm[1024];
    int tid = threadIdx.x;
    int base = tid * (NCELLS / 1024);        // 32 cells per thread
    int s = 0;
    for (int j = 0; j < NCELLS / 1024; j++) s += g_hist[base + j];
    sm[tid] = s;
    __syncthreads();
    for (int off = 1; off < 1024; off <<= 1) {
        int v = (tid >= off) ? sm[tid - off] : 0;
        __syncthreads();
        sm[tid] += v;
        __syncthreads();
    }
    int run = sm[tid] - s;                   // exclusive
    for (int j = 0; j < NCELLS / 1024; j++) {
        g_cellstart[base + j] = run;
        g_cellptr[base + j] = run;
        run += g_hist[base + j];
    }
    if (tid == 1023) g_cellstart[NCELLS] = run;
    __syncthreads();
    for (int i = tid; i < NPTS; i += 1024) {
        int c = g_pcell[i];
        int slot = atomicAdd(&g_cellptr[c], 1);
        g_spts[slot] = g_pts[i];
        g_ssid[slot] = i;
        g_scell[slot] = c;
    }
}

// stable ascending insert of (d, j) into 16-deep register list
__device__ __forceinline__ void insert16(float (&dist)[KNN], int (&idx)[KNN],
                                         float d, int j) {
#pragma unroll
    for (int s = KNN - 1; s >= 0; --s) {
        float cur = dist[s];
        if (d < cur) {
            bool ins = (s == 0) || (d >= dist[s - 1]);
            dist[s] = ins ? d : dist[s - 1];
            idx [s] = ins ? j : idx [s - 1];
        }
    }
}

// ---------------- exact kNN: warp/query, count-then-scan (no distance feedback) ----------------
__global__ void __launch_bounds__(256) knn_query_kernel() {
    int t    = blockIdx.x * 8 + (threadIdx.x >> 5);   // one warp per sorted slot
    int lane = threadIdx.x & 31;
    float4 p = g_spts[t];
    int cc   = g_scell[t];
    int cx = cc & (GD - 1), cy = (cc >> 5) & (GD - 1), cz = cc >> 10;
    float nx = -2.f * p.x, ny = -2.f * p.y, nz = -2.f * p.z;

    // ---- phase 1 (lane 0): smallest cube with >= 17 points, then scan box ----
    int bx0 = 0, bx1 = 0, by0 = 0, by1 = 0, bz0 = 0, bz1 = 0;
    if (lane == 0) {
        int R = 0;
        int cnt = g_cellstart[cc + 1] - g_cellstart[cc];
        while (cnt < KNN + 1 && R < GD) {
            R++;
            int zz0 = max(cz - R, 0), zz1 = min(cz + R, GD - 1);
            int yy0 = max(cy - R, 0), yy1 = min(cy + R, GD - 1);
            int xx0 = max(cx - R, 0), xx1 = min(cx + R, GD - 1);
            cnt = 0;
            for (int z = zz0; z <= zz1; z++)
                for (int y = yy0; y <= yy1; y++) {
                    int rowb = (z << 10) | (y << 5);
                    cnt += g_cellstart[rowb + xx1 + 1] - g_cellstart[rowb + xx0];
                }
        }
        // every point closer than the kth NN lies within D of the query
        float D = (float)(R + 1) * sqrtf(g_gp[7]);
        int rx = (int)(D * g_gp[3]) + 1;
        int ry = (int)(D * g_gp[4]) + 1;
        int rz = (int)(D * g_gp[5]) + 1;
        bx0 = max(cx - rx, 0); bx1 = min(cx + rx, GD - 1);
        by0 = max(cy - ry, 0); by1 = min(cy + ry, GD - 1);
        bz0 = max(cz - rz, 0); bz1 = min(cz + rz, GD - 1);
    }
    bx0 = __shfl_sync(0xffffffffu, bx0, 0);
    bx1 = __shfl_sync(0xffffffffu, bx1, 0);
    by0 = __shfl_sync(0xffffffffu, by0, 0);
    by1 = __shfl_sync(0xffffffffu, by1, 0);
    bz0 = __shfl_sync(0xffffffffu, bz0, 0);
    bz1 = __shfl_sync(0xffffffffu, bz1, 0);

    // ---- phase 2: warp-cooperative scan of box rows (single insert site) ----
    float dist[KNN];
    int   idx [KNN];
#pragma unroll
    for (int u = 0; u < KNN; u++) { dist[u] = __int_as_float(0x7f800000); idx[u] = 0x7fffffff; }

    for (int z = bz0; z <= bz1; z++) {
        for (int y = by0; y <= by1; y++) {
            int rowb = (z << 10) | (y << 5);
            int s0 = g_cellstart[rowb + bx0];
            int s1 = g_cellstart[rowb + bx1 + 1];
            for (int s = s0 + lane; s < s1; s += 32) {
                float4 q = g_spts[s];
                float d = fmaf(nx, q.x, fmaf(ny, q.y, fmaf(nz, q.z, q.w)));
                if (d < dist[KNN - 1] && s != t) {
                    insert16(dist, idx, d, g_ssid[s]);
                }
            }
        }
    }

    // ---- merge 32 sorted lists: 16 rounds of warp-argmin on (fkey(d), id) ----
    unsigned out_id = 0;
#pragma unroll
    for (int u = 0; u < KNN; u++) {
        unsigned long long key =
            ((unsigned long long)fkey(dist[0]) << 32) | (unsigned)idx[0];
        unsigned long long m = key;
#pragma unroll
        for (int o = 16; o > 0; o >>= 1) {
            unsigned long long other = __shfl_xor_sync(0xffffffffu, m, o);
            m = (other < m) ? other : m;
        }
        if (key == m) {                      // unique winner pops its head
#pragma unroll
            for (int s2 = 0; s2 < KNN - 1; s2++) {
                dist[s2] = dist[s2 + 1]; idx[s2] = idx[s2 + 1];
            }
            dist[KNN - 1] = __int_as_float(0x7f800000);
            idx [KNN - 1] = 0x7fffffff;
        }
        if (lane == u) out_id = (unsigned)(m & 0xffffffffu);
    }
    int myid = g_ssid[t];
    if (lane < KNN) g_nbr[myid * KNN + lane] = (int)out_id;
}

// ---------------- weight / bias packing ----------------
__global__ void pack_w_kernel(const float* __restrict__ a, const float* __restrict__ b,
                              const float* __restrict__ c, const float* __restrict__ d,
                              float* __restrict__ dst, int D, int Pp) {
    int i = blockIdx.x * blockDim.x + threadIdx.x;
    if (i >= D * Pp) return;
    int r = i / Pp, col = i - r * Pp;
    float* o = dst + (size_t)r * 4 * Pp + col;
    o[0 * Pp] = a[i]; o[1 * Pp] = b[i]; o[2 * Pp] = c[i]; o[3 * Pp] = d[i];
}

__global__ void pack_b_kernel(const float* __restrict__ a, const float* __restrict__ b,
                              const float* __restrict__ c, const float* __restrict__ d,
                              float* __restrict__ dst, int Pp) {
    int i = blockIdx.x * blockDim.x + threadIdx.x;
    if (i >= Pp) return;
    dst[i] = a[i]; dst[Pp + i] = b[i]; dst[2 * Pp + i] = c[i]; dst[3 * Pp + i] = d[i];
}

// ---------------- big SGEMM: C[N,P] = X[N,D] @ W[D,P] + bias ----------------
#define GBM 128
#define GBN 128
#define GBK 16
__global__ void __launch_bounds__(256)
gemm128_kernel(const float* __restrict__ X, const float* __restrict__ W,
               const float* __restrict__ bias, float* __restrict__ C,
               int D, int P) {
    __shared__ float As[GBK][GBM];
    __shared__ float Bs[GBK][GBN];
    int tid = threadIdx.x;
    int bm = blockIdx.x * GBM;
    int bn = blockIdx.y * GBN;

    int ar = tid >> 1;
    int ak = (tid & 1) << 3;
    int bk = tid >> 5;
    int bc = (tid & 31) << 2;
    int tr = tid >> 4, tc = tid & 15;

    const float* xr = X + (size_t)(bm + ar) * D + ak;
    float acc[8][8] = {};

    for (int k0 = 0; k0 < D; k0 += GBK) {
        float4 a0 = *(const float4*)(xr + k0);
        float4 a1 = *(const float4*)(xr + k0 + 4);
        As[ak + 0][ar] = a0.x; As[ak + 1][ar] = a0.y;
        As[ak + 2][ar] = a0.z; As[ak + 3][ar] = a0.w;
        As[ak + 4][ar] = a1.x; As[ak + 5][ar] = a1.y;
        As[ak + 6][ar] = a1.z; As[ak + 7][ar] = a1.w;
        *(float4*)&Bs[bk][bc] =
            *(const float4*)(W + (size_t)(k0 + bk) * P + bn + bc);
        *(float4*)&Bs[bk + 8][bc] =
            *(const float4*)(W + (size_t)(k0 + bk + 8) * P + bn + bc);
        __syncthreads();
#pragma unroll
        for (int kk = 0; kk < GBK; kk++) {
            float4 av0 = *(const float4*)&As[kk][tr * 8];
            float4 av1 = *(const float4*)&As[kk][tr * 8 + 4];
            float4 bv0 = *(const float4*)&Bs[kk][tc * 8];
            float4 bv1 = *(const float4*)&Bs[kk][tc * 8 + 4];
            float a[8] = {av0.x, av0.y, av0.z, av0.w, av1.x, av1.y, av1.z, av1.w};
            float bb[8] = {bv0.x, bv0.y, bv0.z, bv0.w, bv1.x, bv1.y, bv1.z, bv1.w};
#pragma unroll
            for (int i = 0; i < 8; i++)
#pragma unroll
                for (int j = 0; j < 8; j++)
                    acc[i][j] = fmaf(a[i], bb[j], acc[i][j]);
        }
        __syncthreads();
    }

    float bb0[8];
#pragma unroll
    for (int j = 0; j < 8; j++) bb0[j] = bias[bn + tc * 8 + j];
#pragma unroll
    for (int i = 0; i < 8; i++) {
        size_t row = bm + tr * 8 + i;
        float4 o0 = make_float4(acc[i][0] + bb0[0], acc[i][1] + bb0[1],
                                acc[i][2] + bb0[2], acc[i][3] + bb0[3]);
        float4 o1 = make_float4(acc[i][4] + bb0[4], acc[i][5] + bb0[5],
                                acc[i][6] + bb0[6], acc[i][7] + bb0[7]);
        *(float4*)(C + row * P + bn + tc * 8)     = o0;
        *(float4*)(C + row * P + bn + tc * 8 + 4) = o1;
    }
}

// ---------------- small SGEMM (layer 3, P=12), bounds-checked ----------------
#define BM 64
#define BN 64
#define BKT 16
__global__ void gemm_kernel(const float* __restrict__ X, const float* __restrict__ W,
                            const float* __restrict__ bias, float* __restrict__ C,
                            int D, int P) {
    __shared__ float As[BKT][BM];
    __shared__ float Bs[BKT][BN];
    int bm = blockIdx.x * BM;
    int bn = blockIdx.y * BN;
    int tid = threadIdx.x;
    int tr = tid >> 4, tc = tid & 15;
    float acc[4][4] = {};

    for (int k0 = 0; k0 < D; k0 += BKT) {
        for (int t = tid; t < BM * BKT; t += 256) {
            int m = t >> 4, k = t & 15;
            As[k][m] = X[(size_t)(bm + m) * D + k0 + k];
        }
        for (int t = tid; t < BKT * BN; t += 256) {
            int k = t >> 6, n = t & 63;
            int nn = bn + n;
            Bs[k][n] = (nn < P) ? W[(size_t)(k0 + k) * P + nn] : 0.f;
        }
        __syncthreads();
#pragma unroll
        for (int kk = 0; kk < BKT; kk++) {
            float4 av = *(const float4*)&As[kk][tr * 4];
            float4 bv = *(const float4*)&Bs[kk][tc * 4];
            float a[4] = {av.x, av.y, av.z, av.w};
            float bb[4] = {bv.x, bv.y, bv.z, bv.w};
#pragma unroll
            for (int i = 0; i < 4; i++)
#pragma unroll
                for (int j = 0; j < 4; j++)
                    acc[i][j] = fmaf(a[i], bb[j], acc[i][j]);
        }
        __syncthreads();
    }
#pragma unroll
    for (int i = 0; i < 4; i++) {
        int row = bm + tr * 4 + i;
#pragma unroll
        for (int j = 0; j < 4; j++) {
            int col = bn + tc * 4 + j;
            if (col < P) C[(size_t)row * P + col] = acc[i][j] + bias[col];
        }
    }
}

// ---------------- attention, c=128 layers (block per node); packed QKVS ----------------
__global__ void attn128_kernel(const float* __restrict__ pk,
                               const float* __restrict__ resid,
                               float* __restrict__ outp, int do_tanh) {
    __shared__ float sq[128];
    __shared__ float al[16];
    __shared__ int   nb[16];
    int i = blockIdx.x;
    int t = threadIdx.x;
    if (t < 16) nb[t] = g_nbr[i * 16 + t];
    sq[t] = pk[(size_t)i * 512 + t];            // Q at offset 0
    __syncthreads();

    int w = t >> 5, l = t & 31;
#pragma unroll
    for (int ee = 0; ee < 4; ee++) {
        int e = (w << 2) + ee;
        int j = nb[e];
        const float* kj = pk + (size_t)j * 512 + 128;   // K at offset 128
        float a = sq[l] * kj[l];
        a = fmaf(sq[l + 32], kj[l + 32], a);
        a = fmaf(sq[l + 64], kj[l + 64], a);
        a = fmaf(sq[l + 96], kj[l + 96], a);
#pragma unroll
        for (int o = 16; o > 0; o >>= 1) a += __shfl_xor_sync(0xffffffffu, a, o);
        if (l == 0) al[e] = a * 0.08838834764831845f;   // 1/sqrt(128)
    }
    __syncthreads();
    if (t < 32) {
        float a = (l < 16) ? al[l] : -__int_as_float(0x7f800000);
        float m = a;
#pragma unroll
        for (int o = 16; o > 0; o >>= 1) m = fmaxf(m, __shfl_xor_sync(0xffffffffu, m, o));
        float ex = (l < 16) ? expf(a - m) : 0.f;
        float sm = ex;
#pragma unroll
        for (int o = 16; o > 0; o >>= 1) sm += __shfl_xor_sync(0xffffffffu, sm, o);
        if (l < 16) al[l] = ex / sm;
    }
    __syncthreads();

    float acc = pk[(size_t)i * 512 + 384 + t];          // S at offset 384
#pragma unroll
    for (int e = 0; e < 16; e++)
        acc = fmaf(al[e], pk[(size_t)nb[e] * 512 + 256 + t], acc);  // V at 256
    if (resid) acc += resid[(size_t)i * 128 + t];
    outp[(size_t)i * 128 + t] = do_tanh ? tanhf(acc) : acc;
}

// ---------------- attention, c=3 final layer (warp per node); packed P=12 ----------------
__global__ void attn3_kernel(const float* __restrict__ pk, float* __restrict__ outp) {
    int gt = blockIdx.x * blockDim.x + threadIdx.x;
    int i = gt >> 5;
    int l = gt & 31;
    if (i >= NPTS) return;
    int j = 0;
    float a = -__int_as_float(0x7f800000);
    if (l < 16) {
        j = g_nbr[i * 16 + l];
        float qx = pk[i * 12 + 0], qy = pk[i * 12 + 1], qz = pk[i * 12 + 2];
        a = fmaf(qx, pk[j * 12 + 3], fmaf(qy, pk[j * 12 + 4], qz * pk[j * 12 + 5]))
            * 0.5773502691896258f;   // 1/sqrt(3)
    }
    float m = a;
#pragma unroll
    for (int o = 16; o > 0; o >>= 1) m = fmaxf(m, __shfl_xor_sync(0xffffffffu, m, o));
    float ex = (l < 16) ? expf(a - m) : 0.f;
    float sm = ex;
#pragma unroll
    for (int o = 16; o > 0; o >>= 1) sm += __shfl_xor_sync(0xffffffffu, sm, o);
    float wgt = ex / sm;
    float vx = 0.f, vy = 0.f, vz = 0.f;
    if (l < 16) {
        vx = wgt * pk[j * 12 + 6];
        vy = wgt * pk[j * 12 + 7];
        vz = wgt * pk[j * 12 + 8];
    }
#pragma unroll
    for (int o = 16; o > 0; o >>= 1) {
        vx += __shfl_xor_sync(0xffffffffu, vx, o);
        vy += __shfl_xor_sync(0xffffffffu, vy, o);
        vz += __shfl_xor_sync(0xffffffffu, vz, o);
    }
    if (l == 0) {
        outp[i * 3 + 0] = vx + pk[i * 12 + 9];
        outp[i * 3 + 1] = vy + pk[i * 12 + 10];
        outp[i * 3 + 2] = vz + pk[i * 12 + 11];
    }
}

// ---------------- host ----------------
extern "C" void kernel_launch(void* const* d_in, const int* in_sizes, int n_in,
                              void* d_out, int out_size) {
    const float* x = (const float*)d_in[1];
    const float* W1[4] = {(const float*)d_in[2], (const float*)d_in[4],
                          (const float*)d_in[6], (const float*)d_in[8]};
    const float* B1[4] = {(const float*)d_in[3], (const float*)d_in[5],
                          (const float*)d_in[7], (const float*)d_in[9]};
    const float* W2[4] = {(const float*)d_in[10], (const float*)d_in[12],
                          (const float*)d_in[14], (const float*)d_in[16]};
    const float* B2[4] = {(const float*)d_in[11], (const float*)d_in[13],
                          (const float*)d_in[15], (const float*)d_in[17]};
    const float* W3[4] = {(const float*)d_in[18], (const float*)d_in[20],
                          (const float*)d_in[22], (const float*)d_in[24]};
    const float* B3[4] = {(const float*)d_in[19], (const float*)d_in[21],
                          (const float*)d_in[23], (const float*)d_in[25]};
    float* out = (float*)d_out;

    float *qkvs, *h1, *h2, *Wp1, *Wp2, *Wp3, *Bp1, *Bp2, *Bp3;
    void *hist, *bbmin, *bbmax, *done;
    cudaGetSymbolAddress((void**)&qkvs, g_qkvs);
    cudaGetSymbolAddress((void**)&h1,  g_h1);
    cudaGetSymbolAddress((void**)&h2,  g_h2);
    cudaGetSymbolAddress((void**)&Wp1, g_Wp1);
    cudaGetSymbolAddress((void**)&Wp2, g_Wp2);
    cudaGetSymbolAddress((void**)&Wp3, g_Wp3);
    cudaGetSymbolAddress((void**)&Bp1, g_Bp1);
    cudaGetSymbolAddress((void**)&Bp2, g_Bp2);
    cudaGetSymbolAddress((void**)&Bp3, g_Bp3);
    cudaGetSymbolAddress(&hist,  g_hist);
    cudaGetSymbolAddress(&bbmin, g_bbmin);
    cudaGetSymbolAddress(&bbmax, g_bbmax);
    cudaGetSymbolAddress(&done,  g_done);

    // per-replay state reset (memset nodes, not kernel launches)
    cudaMemsetAsync(hist,  0x00, NCELLS * sizeof(int));
    cudaMemsetAsync(bbmin, 0xFF, 3 * sizeof(unsigned));
    cudaMemsetAsync(bbmax, 0x00, 3 * sizeof(unsigned));
    cudaMemsetAsync(done,  0x00, sizeof(unsigned));

    // slot 4 (ncu capture) = knn_query -> verify the count-then-scan rewrite
    bbox_kernel<<<64, 256>>>(x);                                            // 1
    prep_hist_kernel<<<64, 256>>>(x);                                       // 2
    scan_scatter_kernel<<<1, 1024>>>();                                     // 3
    knn_query_kernel<<<NPTS / 8, 256>>>();                                  // 4 <- profiled

    pack_b_kernel<<<1, 128>>>(B1[0], B1[1], B1[2], B1[3], Bp1, 128);
    pack_b_kernel<<<1, 128>>>(B2[0], B2[1], B2[2], B2[3], Bp2, 128);
    pack_b_kernel<<<1, 128>>>(B3[0], B3[1], B3[2], B3[3], Bp3, 3);
    pack_w_kernel<<<(64 * 128 + 255) / 256, 256>>>(W1[0], W1[1], W1[2], W1[3], Wp1, 64, 128);
    pack_w_kernel<<<(128 * 128 + 255) / 256, 256>>>(W2[0], W2[1], W2[2], W2[3], Wp2, 128, 128);
    pack_w_kernel<<<(128 * 3 + 255) / 256, 256>>>(W3[0], W3[1], W3[2], W3[3], Wp3, 128, 3);

    // layer 1
    {
        dim3 grid(NPTS / GBM, 512 / GBN);
        gemm128_kernel<<<grid, 256>>>(x, Wp1, Bp1, qkvs, 64, 512);
    }
    attn128_kernel<<<NPTS, 128>>>(qkvs, nullptr, h1, 1);

    // layer 2
    {
        dim3 grid(NPTS / GBM, 512 / GBN);
        gemm128_kernel<<<grid, 256>>>(h1, Wp2, Bp2, qkvs, 128, 512);
    }
    attn128_kernel<<<NPTS, 128>>>(qkvs, h1, h2, 1);

    // layer 3
    {
        dim3 grid(NPTS / BM, 1);
        gemm_kernel<<<grid, 256>>>(h2, Wp3, Bp3, qkvs, 128, 12);
    }
    attn3_kernel<<<(NPTS * 32) / 128, 128>>>(qkvs, out);
}

// round 7
// speedup vs baseline: 1.4593x; 1.4593x over previous
#include <cuda_runtime.h>
#include <math.h>

#define NPTS 16384
#define KNN  16
#define GD   32
#define NCELLS (GD * GD * GD)

// ---------------- scratch (device globals; no allocation allowed) ----------------
__device__ float4 g_pts [NPTS];
__device__ float4 g_spts[NPTS];
__device__ int    g_pcell[NPTS];
__device__ int    g_ssid [NPTS];
__device__ int    g_scell[NPTS];
__device__ int    g_hist [NCELLS];
__device__ int    g_cellstart[NCELLS + 1];
__device__ int    g_cellptr  [NCELLS];
__device__ unsigned g_bbmin[3];
__device__ unsigned g_bbmax[3];
__device__ unsigned g_done;
__device__ float  g_gp[8];     // ox,oy,oz, ix,iy,iz, hmin, hdiag2
__device__ int    g_nbr [NPTS * KNN];
__device__ float  g_qkvs[NPTS * 512];
__device__ float  g_h1 [NPTS * 128];
__device__ float  g_h2 [NPTS * 128];
__device__ float  g_Wp1[64  * 512];
__device__ float  g_Wp2[128 * 512];
__device__ float  g_Wp3[128 * 12];
__device__ float  g_Bp1[512];
__device__ float  g_Bp2[512];
__device__ float  g_Bp3[12];

// monotone float <-> unsigned key
__device__ __forceinline__ unsigned fkey(float f) {
    unsigned u = __float_as_uint(f);
    return (u & 0x80000000u) ? ~u : (u | 0x80000000u);
}
__device__ __forceinline__ float funkey(unsigned u) {
    u = (u & 0x80000000u) ? (u & 0x7fffffffu) : ~u;
    return __uint_as_float(u);
}

// ---------------- bbox over coords; last block computes grid params ----------------
__global__ void bbox_kernel(const float* __restrict__ x) {
    __shared__ float smn[3][8], smx[3][8];
    int tid = threadIdx.x;
    int i = blockIdx.x * 256 + tid;          // 64 blocks x 256 = 16384
    float v[3];
    v[0] = x[i * 64 + 0]; v[1] = x[i * 64 + 1]; v[2] = x[i * 64 + 2];
    float mn[3] = {v[0], v[1], v[2]}, mx[3] = {v[0], v[1], v[2]};
#pragma unroll
    for (int o = 16; o > 0; o >>= 1)
#pragma unroll
        for (int d = 0; d < 3; d++) {
            mn[d] = fminf(mn[d], __shfl_xor_sync(0xffffffffu, mn[d], o));
            mx[d] = fmaxf(mx[d], __shfl_xor_sync(0xffffffffu, mx[d], o));
        }
    int w = tid >> 5, l = tid & 31;
    if (l == 0)
#pragma unroll
        for (int d = 0; d < 3; d++) { smn[d][w] = mn[d]; smx[d][w] = mx[d]; }
    __syncthreads();
    if (tid == 0) {
#pragma unroll
        for (int d = 0; d < 3; d++) {
            float a = smn[d][0], b = smx[d][0];
            for (int ww = 1; ww < 8; ww++) {
                a = fminf(a, smn[d][ww]); b = fmaxf(b, smx[d][ww]);
            }
            atomicMin(&g_bbmin[d], fkey(a));
            atomicMax(&g_bbmax[d], fkey(b));
        }
        __threadfence();
        if (atomicAdd(&g_done, 1u) == 63u) {
            float hmin = 1e30f, hd2 = 0.f;
            for (int d = 0; d < 3; d++) {
                float lo = funkey(atomicAdd(&g_bbmin[d], 0u)) - 1e-4f;
                float hi = funkey(atomicAdd(&g_bbmax[d], 0u)) + 1e-4f;
                float h = (hi - lo) / (float)GD;
                g_gp[d] = lo;
                g_gp[3 + d] = (float)GD / (hi - lo);
                hmin = fminf(hmin, h);
                hd2 += h * h;
            }
            g_gp[6] = hmin;
            g_gp[7] = hd2;
        }
    }
}

// ---------------- pack coords + |p|^2, cell assignment, histogram ----------------
__global__ void prep_hist_kernel(const float* __restrict__ x) {
    int i = blockIdx.x * blockDim.x + threadIdx.x;
    if (i >= NPTS) return;
    float a = x[i * 64 + 0], b = x[i * 64 + 1], c = x[i * 64 + 2];
    g_pts[i] = make_float4(a, b, c, a * a + b * b + c * c);
    int cx = min(max((int)((a - g_gp[0]) * g_gp[3]), 0), GD - 1);
    int cy = min(max((int)((b - g_gp[1]) * g_gp[4]), 0), GD - 1);
    int cz = min(max((int)((c - g_gp[2]) * g_gp[5]), 0), GD - 1);
    int cell = (cz << 10) | (cy << 5) | cx;
    g_pcell[i] = cell;
    atomicAdd(&g_hist[cell], 1);
}

// ---------------- single-block scan of 32768 cells + scatter ----------------
__global__ void __launch_bounds__(1024) scan_scatter_kernel() {
    __shared__ int sm[1024];
    int tid = threadIdx.x;
    int base = tid * (NCELLS / 1024);        // 32 cells per thread
    int s = 0;
    for (int j = 0; j < NCELLS / 1024; j++) s += g_hist[base + j];
    sm[tid] = s;
    __syncthreads();
    for (int off = 1; off < 1024; off <<= 1) {
        int v = (tid >= off) ? sm[tid - off] : 0;
        __syncthreads();
        sm[tid] += v;
        __syncthreads();
    }
    int run = sm[tid] - s;                   // exclusive
    for (int j = 0; j < NCELLS / 1024; j++) {
        g_cellstart[base + j] = run;
        g_cellptr[base + j] = run;
        run += g_hist[base + j];
    }
    if (tid == 1023) g_cellstart[NCELLS] = run;
    __syncthreads();
    for (int i = tid; i < NPTS; i += 1024) {
        int c = g_pcell[i];
        int slot = atomicAdd(&g_cellptr[c], 1);
        g_spts[slot] = g_pts[i];
        g_ssid[slot] = i;
        g_scell[slot] = c;
    }
}

// stable ascending insert of (d, j) into 16-deep register list
__device__ __forceinline__ void insert16(float (&dist)[KNN], int (&idx)[KNN],
                                         float d, int j) {
#pragma unroll
    for (int s = KNN - 1; s >= 0; --s) {
        float cur = dist[s];
        if (d < cur) {
            bool ins = (s == 0) || (d >= dist[s - 1]);
            dist[s] = ins ? d : dist[s - 1];
            idx [s] = ins ? j : idx [s - 1];
        }
    }
}

// warp-count points in clamped cube of Chebyshev radius R around (cx,cy,cz)
__device__ __forceinline__ int count_cube(int cx, int cy, int cz, int R, int lane) {
    int z0 = max(cz - R, 0), z1 = min(cz + R, GD - 1);
    int y0 = max(cy - R, 0), y1 = min(cy + R, GD - 1);
    int x0 = max(cx - R, 0), x1 = min(cx + R, GD - 1);
    int nyw = y1 - y0 + 1;
    int nrows = (z1 - z0 + 1) * nyw;
    int c = 0;
    for (int r = lane; r < nrows; r += 32) {
        int z = z0 + r / nyw, y = y0 + r % nyw;
        int rowb = (z << 10) | (y << 5);
        c += g_cellstart[rowb + x1 + 1] - g_cellstart[rowb + x0];
    }
#pragma unroll
    for (int o = 16; o > 0; o >>= 1) c += __shfl_xor_sync(0xffffffffu, c, o);
    return c;
}

// warp-cooperative scan of a clamped cell box; rows culled against kt (true d^2 bound)
__device__ __forceinline__ void scan_box(int x0, int x1, int y0, int y1,
                                         int z0, int z1, int lane, int self,
                                         float4 p, float nx, float ny, float nz,
                                         float kt,
                                         float (&dist)[KNN], int (&idx)[KNN]) {
    float oy = g_gp[1], ozf = g_gp[2];
    float hy = 1.f / g_gp[4], hz = 1.f / g_gp[5];
    for (int z = z0; z <= z1; z++) {
        float zlo = fmaf((float)z, hz, ozf);
        float dz = fmaxf(fmaxf(zlo - p.z, p.z - (zlo + hz)), 0.f);
        float dz2 = dz * dz;
        if (dz2 > kt) continue;
        for (int y = y0; y <= y1; y++) {
            float ylo = fmaf((float)y, hy, oy);
            float dy = fmaxf(fmaxf(ylo - p.y, p.y - (ylo + hy)), 0.f);
            if (fmaf(dy, dy, dz2) > kt) continue;
            int rowb = (z << 10) | (y << 5);
            int s0 = g_cellstart[rowb + x0];
            int s1 = g_cellstart[rowb + x1 + 1];
            for (int s = s0 + lane; s < s1; s += 32) {
                float4 q = g_spts[s];
                float d = fmaf(nx, q.x, fmaf(ny, q.y, fmaf(nz, q.z, q.w)));
                if (d < dist[KNN - 1] && s != self) {
                    insert16(dist, idx, d, g_ssid[s]);
                }
            }
        }
    }
}

// 16-round warp-argmin merge of 32 sorted lists; returns d of the 16th popped.
// out_id receives the u-th neighbor id on lane u.
__device__ __forceinline__ float merge_warp(float (&dist)[KNN], int (&idx)[KNN],
                                            int lane, unsigned &out_id) {
    unsigned long long m = 0;
#pragma unroll
    for (int u = 0; u < KNN; u++) {
        unsigned long long key =
            ((unsigned long long)fkey(dist[0]) << 32) | (unsigned)idx[0];
        m = key;
#pragma unroll
        for (int o = 16; o > 0; o >>= 1) {
            unsigned long long other = __shfl_xor_sync(0xffffffffu, m, o);
            m = (other < m) ? other : m;
        }
        if (key == m) {                      // unique winner pops its head
#pragma unroll
            for (int s2 = 0; s2 < KNN - 1; s2++) {
                dist[s2] = dist[s2 + 1]; idx[s2] = idx[s2 + 1];
            }
            dist[KNN - 1] = __int_as_float(0x7f800000);
            idx [KNN - 1] = 0x7fffffff;
        }
        if (lane == u) out_id = (unsigned)(m & 0xffffffffu);
    }
    return funkey((unsigned)(m >> 32));      // 16th smallest d
}

// ---------------- exact kNN: warp/query, two-phase with exact distance bound ----------------
__global__ void __launch_bounds__(256) knn_query_kernel() {
    int t    = blockIdx.x * 8 + (threadIdx.x >> 5);   // one warp per sorted slot
    int lane = threadIdx.x & 31;
    float4 p = g_spts[t];
    int cc   = g_scell[t];
    int cx = cc & (GD - 1), cy = (cc >> 5) & (GD - 1), cz = cc >> 10;
    float nx = -2.f * p.x, ny = -2.f * p.y, nz = -2.f * p.z;
    int myid = g_ssid[t];

    // ---- phase A: smallest cube with >= 17 points (incl. self) ----
    int R = 0;
    int cnt = g_cellstart[cc + 1] - g_cellstart[cc];
    while (cnt < KNN + 1 && R < GD) {
        R++;
        cnt = count_cube(cx, cy, cz, R, lane);
    }

    float dist[KNN];
    int   idx [KNN];
#pragma unroll
    for (int u = 0; u < KNN; u++) { dist[u] = __int_as_float(0x7f800000); idx[u] = 0x7fffffff; }

    int az0 = max(cz - R, 0), az1 = min(cz + R, GD - 1);
    int ay0 = max(cy - R, 0), ay1 = min(cy + R, GD - 1);
    int ax0 = max(cx - R, 0), ax1 = min(cx + R, GD - 1);
    scan_box(ax0, ax1, ay0, ay1, az0, az1, lane, t, p, nx, ny, nz,
             __int_as_float(0x7f800000), dist, idx);

    unsigned out_id = 0;
    float d16 = merge_warp(dist, idx, lane, out_id);

    // true-squared upper bound on the global kth distance (inflated for fp safety)
    float kt = fmaxf(d16 + p.w, 0.f) * 1.0002f + 1e-12f;
    float rho = sqrtf(kt);
    int rx = (int)(rho * g_gp[3]) + 1;
    int ry = (int)(rho * g_gp[4]) + 1;
    int rz = (int)(rho * g_gp[5]) + 1;

    if (rx > R || ry > R || rz > R) {
        // ---- phase B: tight box with row culling, fresh lists ----
#pragma unroll
        for (int u = 0; u < KNN; u++) { dist[u] = __int_as_float(0x7f800000); idx[u] = 0x7fffffff; }
        int bx0 = max(cx - rx, 0), bx1 = min(cx + rx, GD - 1);
        int by0 = max(cy - ry, 0), by1 = min(cy + ry, GD - 1);
        int bz0 = max(cz - rz, 0), bz1 = min(cz + rz, GD - 1);
        scan_box(bx0, bx1, by0, by1, bz0, bz1, lane, t, p, nx, ny, nz,
                 kt, dist, idx);
        merge_warp(dist, idx, lane, out_id);
    }

    if (lane < KNN) g_nbr[myid * KNN + lane] = (int)out_id;
}

// ---------------- weight / bias packing ----------------
__global__ void pack_w_kernel(const float* __restrict__ a, const float* __restrict__ b,
                              const float* __restrict__ c, const float* __restrict__ d,
                              float* __restrict__ dst, int D, int Pp) {
    int i = blockIdx.x * blockDim.x + threadIdx.x;
    if (i >= D * Pp) return;
    int r = i / Pp, col = i - r * Pp;
    float* o = dst + (size_t)r * 4 * Pp + col;
    o[0 * Pp] = a[i]; o[1 * Pp] = b[i]; o[2 * Pp] = c[i]; o[3 * Pp] = d[i];
}

__global__ void pack_b_kernel(const float* __restrict__ a, const float* __restrict__ b,
                              const float* __restrict__ c, const float* __restrict__ d,
                              float* __restrict__ dst, int Pp) {
    int i = blockIdx.x * blockDim.x + threadIdx.x;
    if (i >= Pp) return;
    dst[i] = a[i]; dst[Pp + i] = b[i]; dst[2 * Pp + i] = c[i]; dst[3 * Pp + i] = d[i];
}

// ---------------- big SGEMM: C[N,P] = X[N,D] @ W[D,P] + bias ----------------
#define GBM 128
#define GBN 128
#define GBK 16
__global__ void __launch_bounds__(256)
gemm128_kernel(const float* __restrict__ X, const float* __restrict__ W,
               const float* __restrict__ bias, float* __restrict__ C,
               int D, int P) {
    __shared__ float As[GBK][GBM];
    __shared__ float Bs[GBK][GBN];
    int tid = threadIdx.x;
    int bm = blockIdx.x * GBM;
    int bn = blockIdx.y * GBN;

    int ar = tid >> 1;
    int ak = (tid & 1) << 3;
    int bk = tid >> 5;
    int bc = (tid & 31) << 2;
    int tr = tid >> 4, tc = tid & 15;

    const float* xr = X + (size_t)(bm + ar) * D + ak;
    float acc[8][8] = {};

    for (int k0 = 0; k0 < D; k0 += GBK) {
        float4 a0 = *(const float4*)(xr + k0);
        float4 a1 = *(const float4*)(xr + k0 + 4);
        As[ak + 0][ar] = a0.x; As[ak + 1][ar] = a0.y;
        As[ak + 2][ar] = a0.z; As[ak + 3][ar] = a0.w;
        As[ak + 4][ar] = a1.x; As[ak + 5][ar] = a1.y;
        As[ak + 6][ar] = a1.z; As[ak + 7][ar] = a1.w;
        *(float4*)&Bs[bk][bc] =
            *(const float4*)(W + (size_t)(k0 + bk) * P + bn + bc);
        *(float4*)&Bs[bk + 8][bc] =
            *(const float4*)(W + (size_t)(k0 + bk + 8) * P + bn + bc);
        __syncthreads();
#pragma unroll
        for (int kk = 0; kk < GBK; kk++) {
            float4 av0 = *(const float4*)&As[kk][tr * 8];
            float4 av1 = *(const float4*)&As[kk][tr * 8 + 4];
            float4 bv0 = *(const float4*)&Bs[kk][tc * 8];
            float4 bv1 = *(const float4*)&Bs[kk][tc * 8 + 4];
            float a[8] = {av0.x, av0.y, av0.z, av0.w, av1.x, av1.y, av1.z, av1.w};
            float bb[8] = {bv0.x, bv0.y, bv0.z, bv0.w, bv1.x, bv1.y, bv1.z, bv1.w};
#pragma unroll
            for (int i = 0; i < 8; i++)
#pragma unroll
                for (int j = 0; j < 8; j++)
                    acc[i][j] = fmaf(a[i], bb[j], acc[i][j]);
        }
        __syncthreads();
    }

    float bb0[8];
#pragma unroll
    for (int j = 0; j < 8; j++) bb0[j] = bias[bn + tc * 8 + j];
#pragma unroll
    for (int i = 0; i < 8; i++) {
        size_t row = bm + tr * 8 + i;
        float4 o0 = make_float4(acc[i][0] + bb0[0], acc[i][1] + bb0[1],
                                acc[i][2] + bb0[2], acc[i][3] + bb0[3]);
        float4 o1 = make_float4(acc[i][4] + bb0[4], acc[i][5] + bb0[5],
                                acc[i][6] + bb0[6], acc[i][7] + bb0[7]);
        *(float4*)(C + row * P + bn + tc * 8)     = o0;
        *(float4*)(C + row * P + bn + tc * 8 + 4) = o1;
    }
}

// ---------------- small SGEMM (layer 3, P=12), bounds-checked ----------------
#define BM 64
#define BN 64
#define BKT 16
__global__ void gemm_kernel(const float* __restrict__ X, const float* __restrict__ W,
                            const float* __restrict__ bias, float* __restrict__ C,
                            int D, int P) {
    __shared__ float As[BKT][BM];
    __shared__ float Bs[BKT][BN];
    int bm = blockIdx.x * BM;
    int bn = blockIdx.y * BN;
    int tid = threadIdx.x;
    int tr = tid >> 4, tc = tid & 15;
    float acc[4][4] = {};

    for (int k0 = 0; k0 < D; k0 += BKT) {
        for (int t = tid; t < BM * BKT; t += 256) {
            int m = t >> 4, k = t & 15;
            As[k][m] = X[(size_t)(bm + m) * D + k0 + k];
        }
        for (int t = tid; t < BKT * BN; t += 256) {
            int k = t >> 6, n = t & 63;
            int nn = bn + n;
            Bs[k][n] = (nn < P) ? W[(size_t)(k0 + k) * P + nn] : 0.f;
        }
        __syncthreads();
#pragma unroll
        for (int kk = 0; kk < BKT; kk++) {
            float4 av = *(const float4*)&As[kk][tr * 4];
            float4 bv = *(const float4*)&Bs[kk][tc * 4];
            float a[4] = {av.x, av.y, av.z, av.w};
            float bb[4] = {bv.x, bv.y, bv.z, bv.w};
#pragma unroll
            for (int i = 0; i < 4; i++)
#pragma unroll
                for (int j = 0; j < 4; j++)
                    acc[i][j] = fmaf(a[i], bb[j], acc[i][j]);
        }
        __syncthreads();
    }
#pragma unroll
    for (int i = 0; i < 4; i++) {
        int row = bm + tr * 4 + i;
#pragma unroll
        for (int j = 0; j < 4; j++) {
            int col = bn + tc * 4 + j;
            if (col < P) C[(size_t)row * P + col] = acc[i][j] + bias[col];
        }
    }
}

// ---------------- attention, c=128 layers (block per node); packed QKVS ----------------
__global__ void attn128_kernel(const float* __restrict__ pk,
                               const float* __restrict__ resid,
                               float* __restrict__ outp, int do_tanh) {
    __shared__ float sq[128];
    __shared__ float al[16];
    __shared__ int   nb[16];
    int i = blockIdx.x;
    int t = threadIdx.x;
    if (t < 16) nb[t] = g_nbr[i * 16 + t];
    sq[t] = pk[(size_t)i * 512 + t];            // Q at offset 0
    __syncthreads();

    int w = t >> 5, l = t & 31;
#pragma unroll
    for (int ee = 0; ee < 4; ee++) {
        int e = (w << 2) + ee;
        int j = nb[e];
        const float* kj = pk + (size_t)j * 512 + 128;   // K at offset 128
        float a = sq[l] * kj[l];
        a = fmaf(sq[l + 32], kj[l + 32], a);
        a = fmaf(sq[l + 64], kj[l + 64], a);
        a = fmaf(sq[l + 96], kj[l + 96], a);
#pragma unroll
        for (int o = 16; o > 0; o >>= 1) a += __shfl_xor_sync(0xffffffffu, a, o);
        if (l == 0) al[e] = a * 0.08838834764831845f;   // 1/sqrt(128)
    }
    __syncthreads();
    if (t < 32) {
        float a = (l < 16) ? al[l] : -__int_as_float(0x7f800000);
        float m = a;
#pragma unroll
        for (int o = 16; o > 0; o >>= 1) m = fmaxf(m, __shfl_xor_sync(0xffffffffu, m, o));
        float ex = (l < 16) ? expf(a - m) : 0.f;
        float sm = ex;
#pragma unroll
        for (int o = 16; o > 0; o >>= 1) sm += __shfl_xor_sync(0xffffffffu, sm, o);
        if (l < 16) al[l] = ex / sm;
    }
    __syncthreads();

    float acc = pk[(size_t)i * 512 + 384 + t];          // S at offset 384
#pragma unroll
    for (int e = 0; e < 16; e++)
        acc = fmaf(al[e], pk[(size_t)nb[e] * 512 + 256 + t], acc);  // V at 256
    if (resid) acc += resid[(size_t)i * 128 + t];
    outp[(size_t)i * 128 + t] = do_tanh ? tanhf(acc) : acc;
}

// ---------------- attention, c=3 final layer (warp per node); packed P=12 ----------------
__global__ void attn3_kernel(const float* __restrict__ pk, float* __restrict__ outp) {
    int gt = blockIdx.x * blockDim.x + threadIdx.x;
    int i = gt >> 5;
    int l = gt & 31;
    if (i >= NPTS) return;
    int j = 0;
    float a = -__int_as_float(0x7f800000);
    if (l < 16) {
        j = g_nbr[i * 16 + l];
        float qx = pk[i * 12 + 0], qy = pk[i * 12 + 1], qz = pk[i * 12 + 2];
        a = fmaf(qx, pk[j * 12 + 3], fmaf(qy, pk[j * 12 + 4], qz * pk[j * 12 + 5]))
            * 0.5773502691896258f;   // 1/sqrt(3)
    }
    float m = a;
#pragma unroll
    for (int o = 16; o > 0; o >>= 1) m = fmaxf(m, __shfl_xor_sync(0xffffffffu, m, o));
    float ex = (l < 16) ? expf(a - m) : 0.f;
    float sm = ex;
#pragma unroll
    for (int o = 16; o > 0; o >>= 1) sm += __shfl_xor_sync(0xffffffffu, sm, o);
    float wgt = ex / sm;
    float vx = 0.f, vy = 0.f, vz = 0.f;
    if (l < 16) {
        vx = wgt * pk[j * 12 + 6];
        vy = wgt * pk[j * 12 + 7];
        vz = wgt * pk[j * 12 + 8];
    }
#pragma unroll
    for (int o = 16; o > 0; o >>= 1) {
        vx += __shfl_xor_sync(0xffffffffu, vx, o);
        vy += __shfl_xor_sync(0xffffffffu, vy, o);
        vz += __shfl_xor_sync(0xffffffffu, vz, o);
    }
    if (l == 0) {
        outp[i * 3 + 0] = vx + pk[i * 12 + 9];
        outp[i * 3 + 1] = vy + pk[i * 12 + 10];
        outp[i * 3 + 2] = vz + pk[i * 12 + 11];
    }
}

// ---------------- host ----------------
extern "C" void kernel_launch(void* const* d_in, const int* in_sizes, int n_in,
                              void* d_out, int out_size) {
    const float* x = (const float*)d_in[1];
    const float* W1[4] = {(const float*)d_in[2], (const float*)d_in[4],
                          (const float*)d_in[6], (const float*)d_in[8]};
    const float* B1[4] = {(const float*)d_in[3], (const float*)d_in[5],
                          (const float*)d_in[7], (const float*)d_in[9]};
    const float* W2[4] = {(const float*)d_in[10], (const float*)d_in[12],
                          (const float*)d_in[14], (const float*)d_in[16]};
    const float* B2[4] = {(const float*)d_in[11], (const float*)d_in[13],
                          (const float*)d_in[15], (const float*)d_in[17]};
    const float* W3[4] = {(const float*)d_in[18], (const float*)d_in[20],
                          (const float*)d_in[22], (const float*)d_in[24]};
    const float* B3[4] = {(const float*)d_in[19], (const float*)d_in[21],
                          (const float*)d_in[23], (const float*)d_in[25]};
    float* out = (float*)d_out;

    float *qkvs, *h1, *h2, *Wp1, *Wp2, *Wp3, *Bp1, *Bp2, *Bp3;
    void *hist, *bbmin, *bbmax, *done;
    cudaGetSymbolAddress((void**)&qkvs, g_qkvs);
    cudaGetSymbolAddress((void**)&h1,  g_h1);
    cudaGetSymbolAddress((void**)&h2,  g_h2);
    cudaGetSymbolAddress((void**)&Wp1, g_Wp1);
    cudaGetSymbolAddress((void**)&Wp2, g_Wp2);
    cudaGetSymbolAddress((void**)&Wp3, g_Wp3);
    cudaGetSymbolAddress((void**)&Bp1, g_Bp1);
    cudaGetSymbolAddress((void**)&Bp2, g_Bp2);
    cudaGetSymbolAddress((void**)&Bp3, g_Bp3);
    cudaGetSymbolAddress(&hist,  g_hist);
    cudaGetSymbolAddress(&bbmin, g_bbmin);
    cudaGetSymbolAddress(&bbmax, g_bbmax);
    cudaGetSymbolAddress(&done,  g_done);

    // per-replay state reset (memset nodes, not kernel launches)
    cudaMemsetAsync(hist,  0x00, NCELLS * sizeof(int));
    cudaMemsetAsync(bbmin, 0xFF, 3 * sizeof(unsigned));
    cudaMemsetAsync(bbmax, 0x00, 3 * sizeof(unsigned));
    cudaMemsetAsync(done,  0x00, sizeof(unsigned));

    // slot 4 (ncu capture) = knn_query -> verify the two-phase rewrite
    bbox_kernel<<<64, 256>>>(x);                                            // 1
    prep_hist_kernel<<<64, 256>>>(x);                                       // 2
    scan_scatter_kernel<<<1, 1024>>>();                                     // 3
    knn_query_kernel<<<NPTS / 8, 256>>>();                                  // 4 <- profiled

    pack_b_kernel<<<1, 128>>>(B1[0], B1[1], B1[2], B1[3], Bp1, 128);
    pack_b_kernel<<<1, 128>>>(B2[0], B2[1], B2[2], B2[3], Bp2, 128);
    pack_b_kernel<<<1, 128>>>(B3[0], B3[1], B3[2], B3[3], Bp3, 3);
    pack_w_kernel<<<(64 * 128 + 255) / 256, 256>>>(W1[0], W1[1], W1[2], W1[3], Wp1, 64, 128);
    pack_w_kernel<<<(128 * 128 + 255) / 256, 256>>>(W2[0], W2[1], W2[2], W2[3], Wp2, 128, 128);
    pack_w_kernel<<<(128 * 3 + 255) / 256, 256>>>(W3[0], W3[1], W3[2], W3[3], Wp3, 128, 3);

    // layer 1
    {
        dim3 grid(NPTS / GBM, 512 / GBN);
        gemm128_kernel<<<grid, 256>>>(x, Wp1, Bp1, qkvs, 64, 512);
    }
    attn128_kernel<<<NPTS, 128>>>(qkvs, nullptr, h1, 1);

    // layer 2
    {
        dim3 grid(NPTS / GBM, 512 / GBN);
        gemm128_kernel<<<grid, 256>>>(h1, Wp2, Bp2, qkvs, 128, 512);
    }
    attn128_kernel<<<NPTS, 128>>>(qkvs, h1, h2, 1);

    // layer 3
    {
        dim3 grid(NPTS / BM, 1);
        gemm_kernel<<<grid, 256>>>(h2, Wp3, Bp3, qkvs, 128, 12);
    }
    attn3_kernel<<<(NPTS * 32) / 128, 128>>>(qkvs, out);
}

// round 9
// speedup vs baseline: 1.5221x; 1.0430x over previous
#include <cuda_runtime.h>
#include <math.h>

#define NPTS 16384
#define KNN  16
#define LK   16          // per-lane list depth = KNN: provably exact (lane bias safe)
#define GD   32
#define NCELLS (GD * GD * GD)

// ---------------- scratch (device globals; no allocation allowed) ----------------
__device__ float4 g_pts [NPTS];
__device__ float4 g_spts[NPTS];
__device__ int    g_pcell[NPTS];
__device__ int    g_rank [NPTS];
__device__ int    g_ssid [NPTS];
__device__ int    g_scell[NPTS];
__device__ int    g_hist [NCELLS];
__device__ int    g_cellstart[NCELLS + 1];
__device__ unsigned g_bbmin[3];
__device__ unsigned g_bbmax[3];
__device__ unsigned g_done;
__device__ float  g_gp[8];     // ox,oy,oz, ix,iy,iz, hmin, hdiag2
__device__ int    g_nbr [NPTS * KNN];
__device__ float  g_qkvs[NPTS * 512];
__device__ float  g_h1 [NPTS * 128];
__device__ float  g_h2 [NPTS * 128];
__device__ float  g_Wp1[64  * 512];
__device__ float  g_Wp2[128 * 512];
__device__ float  g_Wp3[128 * 12];
__device__ float  g_Bp1[512];
__device__ float  g_Bp2[512];
__device__ float  g_Bp3[12];

// monotone float <-> unsigned key
__device__ __forceinline__ unsigned fkey(float f) {
    unsigned u = __float_as_uint(f);
    return (u & 0x80000000u) ? ~u : (u | 0x80000000u);
}
__device__ __forceinline__ float funkey(unsigned u) {
    u = (u & 0x80000000u) ? (u & 0x7fffffffu) : ~u;
    return __uint_as_float(u);
}

// ---------------- bbox over coords; last block computes grid params ----------------
__global__ void bbox_kernel(const float* __restrict__ x) {
    __shared__ float smn[3][8], smx[3][8];
    int tid = threadIdx.x;
    int i = blockIdx.x * 256 + tid;          // 64 blocks x 256 = 16384
    float v[3];
    v[0] = x[i * 64 + 0]; v[1] = x[i * 64 + 1]; v[2] = x[i * 64 + 2];
    float mn[3] = {v[0], v[1], v[2]}, mx[3] = {v[0], v[1], v[2]};
#pragma unroll
    for (int o = 16; o > 0; o >>= 1)
#pragma unroll
        for (int d = 0; d < 3; d++) {
            mn[d] = fminf(mn[d], __shfl_xor_sync(0xffffffffu, mn[d], o));
            mx[d] = fmaxf(mx[d], __shfl_xor_sync(0xffffffffu, mx[d], o));
        }
    int w = tid >> 5, l = tid & 31;
    if (l == 0)
#pragma unroll
        for (int d = 0; d < 3; d++) { smn[d][w] = mn[d]; smx[d][w] = mx[d]; }
    __syncthreads();
    if (tid == 0) {
#pragma unroll
        for (int d = 0; d < 3; d++) {
            float a = smn[d][0], b = smx[d][0];
            for (int ww = 1; ww < 8; ww++) {
                a = fminf(a, smn[d][ww]); b = fmaxf(b, smx[d][ww]);
            }
            atomicMin(&g_bbmin[d], fkey(a));
            atomicMax(&g_bbmax[d], fkey(b));
        }
        __threadfence();
        if (atomicAdd(&g_done, 1u) == 63u) {
            float hmin = 1e30f, hd2 = 0.f;
            for (int d = 0; d < 3; d++) {
                float lo = funkey(atomicAdd(&g_bbmin[d], 0u)) - 1e-4f;
                float hi = funkey(atomicAdd(&g_bbmax[d], 0u)) + 1e-4f;
                float h = (hi - lo) / (float)GD;
                g_gp[d] = lo;
                g_gp[3 + d] = (float)GD / (hi - lo);
                hmin = fminf(hmin, h);
                hd2 += h * h;
            }
            g_gp[6] = hmin;
            g_gp[7] = hd2;
        }
    }
}

// ---------------- pack coords + |p|^2, cell assignment, histogram + rank ----------------
__global__ void prep_hist_kernel(const float* __restrict__ x) {
    int i = blockIdx.x * blockDim.x + threadIdx.x;
    if (i >= NPTS) return;
    float a = x[i * 64 + 0], b = x[i * 64 + 1], c = x[i * 64 + 2];
    g_pts[i] = make_float4(a, b, c, a * a + b * b + c * c);
    int cx = min(max((int)((a - g_gp[0]) * g_gp[3]), 0), GD - 1);
    int cy = min(max((int)((b - g_gp[1]) * g_gp[4]), 0), GD - 1);
    int cz = min(max((int)((c - g_gp[2]) * g_gp[5]), 0), GD - 1);
    int cell = (cz << 10) | (cy << 5) | cx;
    g_pcell[i] = cell;
    g_rank[i] = atomicAdd(&g_hist[cell], 1);    // within-cell rank (free)
}

// ---------------- single-block scan; atomic-free direct-slot scatter ----------------
__global__ void __launch_bounds__(1024) scan_scatter_kernel() {
    __shared__ int sm[1024];
    int tid = threadIdx.x;
    int base = tid * (NCELLS / 1024);        // 32 cells per thread
    int s = 0;
    for (int j = 0; j < NCELLS / 1024; j++) s += g_hist[base + j];
    sm[tid] = s;
    __syncthreads();
    for (int off = 1; off < 1024; off <<= 1) {
        int v = (tid >= off) ? sm[tid - off] : 0;
        __syncthreads();
        sm[tid] += v;
        __syncthreads();
    }
    int run = sm[tid] - s;                   // exclusive
    for (int j = 0; j < NCELLS / 1024; j++) {
        g_cellstart[base + j] = run;
        run += g_hist[base + j];
    }
    if (tid == 1023) g_cellstart[NCELLS] = run;
    __syncthreads();
    // direct-slot scatter: slot = cellstart[c] + rank  (no atomics)
    for (int i = tid; i < NPTS; i += 1024) {
        int c = g_pcell[i];
        int slot = g_cellstart[c] + g_rank[i];
        g_spts[slot] = g_pts[i];
        g_ssid[slot] = i;
        g_scell[slot] = c;
    }
}

// stable ascending insert of (d, j) into LK-deep register list
__device__ __forceinline__ void insertL(float (&dist)[LK], int (&idx)[LK],
                                        float d, int j) {
#pragma unroll
    for (int s = LK - 1; s >= 0; --s) {
        float cur = dist[s];
        if (d < cur) {
            bool ins = (s == 0) || (d >= dist[s - 1]);
            dist[s] = ins ? d : dist[s - 1];
            idx [s] = ins ? j : idx [s - 1];
        }
    }
}

// warp-count points in clamped cube of Chebyshev radius R around (cx,cy,cz)
__device__ __forceinline__ int count_cube(int cx, int cy, int cz, int R, int lane) {
    int z0 = max(cz - R, 0), z1 = min(cz + R, GD - 1);
    int y0 = max(cy - R, 0), y1 = min(cy + R, GD - 1);
    int x0 = max(cx - R, 0), x1 = min(cx + R, GD - 1);
    int nyw = y1 - y0 + 1;
    int nrows = (z1 - z0 + 1) * nyw;
    int c = 0;
    for (int r = lane; r < nrows; r += 32) {
        int z = z0 + r / nyw, y = y0 + r % nyw;
        int rowb = (z << 10) | (y << 5);
        c += g_cellstart[rowb + x1 + 1] - g_cellstart[rowb + x0];
    }
#pragma unroll
    for (int o = 16; o > 0; o >>= 1) c += __shfl_xor_sync(0xffffffffu, c, o);
    return c;
}

// ---------------- exact kNN: warp/query, phase loop, single scan/merge site ----------------
__global__ void __launch_bounds__(256) knn_query_kernel() {
    int t    = blockIdx.x * 8 + (threadIdx.x >> 5);   // one warp per sorted slot
    int lane = threadIdx.x & 31;
    float4 p = g_spts[t];
    int cc   = g_scell[t];
    int cx = cc & (GD - 1), cy = (cc >> 5) & (GD - 1), cz = cc >> 10;
    float nx = -2.f * p.x, ny = -2.f * p.y, nz = -2.f * p.z;
    int myid = g_ssid[t];

    // smallest cube with >= 17 points (incl. self)
    int R = 0;
    int cnt = g_cellstart[cc + 1] - g_cellstart[cc];
    while (cnt < KNN + 1 && R < GD) {
        R++;
        cnt = count_cube(cx, cy, cz, R, lane);
    }

    float oy = g_gp[1], ozf = g_gp[2];
    float hy = 1.f / g_gp[4], hz = 1.f / g_gp[5];

    float dist[LK];
    int   idx [LK];
    unsigned out_id = 0;
    float kt = __int_as_float(0x7f800000);
    int rx = R, ry = R, rz = R;

    for (int phase = 0; phase < 2; phase++) {
#pragma unroll
        for (int u = 0; u < LK; u++) { dist[u] = __int_as_float(0x7f800000); idx[u] = 0x7fffffff; }

        int bx0 = max(cx - rx, 0), bx1 = min(cx + rx, GD - 1);
        int by0 = max(cy - ry, 0), by1 = min(cy + ry, GD - 1);
        int bz0 = max(cz - rz, 0), bz1 = min(cz + rz, GD - 1);

        // ---- scan box, rows culled against kt (true squared distance bound) ----
        for (int z = bz0; z <= bz1; z++) {
            float zlo = fmaf((float)z, hz, ozf);
            float dzc = fmaxf(fmaxf(zlo - p.z, p.z - (zlo + hz)), 0.f);
            float dz2 = dzc * dzc;
            if (dz2 > kt) continue;
            for (int y = by0; y <= by1; y++) {
                float ylo = fmaf((float)y, hy, oy);
                float dyc = fmaxf(fmaxf(ylo - p.y, p.y - (ylo + hy)), 0.f);
                if (fmaf(dyc, dyc, dz2) > kt) continue;
                int rowb = (z << 10) | (y << 5);
                int s0 = g_cellstart[rowb + bx0];
                int s1 = g_cellstart[rowb + bx1 + 1];
                for (int s = s0 + lane; s < s1; s += 32) {
                    float4 q = g_spts[s];
                    float d = fmaf(nx, q.x, fmaf(ny, q.y, fmaf(nz, q.z, q.w)));
                    if (d < dist[LK - 1] && s != t) {
                        insertL(dist, idx, d, g_ssid[s]);
                    }
                }
            }
        }

        // ---- merge 32 sorted lists: 16 rounds of warp-argmin on (fkey(d), id) ----
        unsigned long long m = 0;
#pragma unroll
        for (int u = 0; u < KNN; u++) {
            unsigned long long key =
                ((unsigned long long)fkey(dist[0]) << 32) | (unsigned)idx[0];
            m = key;
#pragma unroll
            for (int o = 16; o > 0; o >>= 1) {
                unsigned long long other = __shfl_xor_sync(0xffffffffu, m, o);
                m = (other < m) ? other : m;
            }
            if (key == m) {                  // winner pops its head
#pragma unroll
                for (int s2 = 0; s2 < LK - 1; s2++) {
                    dist[s2] = dist[s2 + 1]; idx[s2] = idx[s2 + 1];
                }
                dist[LK - 1] = __int_as_float(0x7f800000);
                idx [LK - 1] = 0x7fffffff;
            }
            if (lane == u) out_id = (unsigned)(m & 0xffffffffu);
        }
        if (phase) break;
        float d16 = funkey((unsigned)(m >> 32));    // 16th smallest shifted d

        // true-squared upper bound on the global kth distance (inflated for fp safety)
        float nkt = fmaxf(d16 + p.w, 0.f) * 1.0002f + 1e-12f;
        float rho = sqrtf(nkt);
        int nrx = (int)(rho * g_gp[3]) + 1;
        int nry = (int)(rho * g_gp[4]) + 1;
        int nrz = (int)(rho * g_gp[5]) + 1;
        if (nrx <= rx && nry <= ry && nrz <= rz) break;   // cube already covers ball
        kt = nkt; rx = nrx; ry = nry; rz = nrz;
    }

    if (lane < KNN) g_nbr[myid * KNN + lane] = (int)out_id;
}

// ---------------- weight / bias packing ----------------
__global__ void pack_w_kernel(const float* __restrict__ a, const float* __restrict__ b,
                              const float* __restrict__ c, const float* __restrict__ d,
                              float* __restrict__ dst, int D, int Pp) {
    int i = blockIdx.x * blockDim.x + threadIdx.x;
    if (i >= D * Pp) return;
    int r = i / Pp, col = i - r * Pp;
    float* o = dst + (size_t)r * 4 * Pp + col;
    o[0 * Pp] = a[i]; o[1 * Pp] = b[i]; o[2 * Pp] = c[i]; o[3 * Pp] = d[i];
}

__global__ void pack_b_kernel(const float* __restrict__ a, const float* __restrict__ b,
                              const float* __restrict__ c, const float* __restrict__ d,
                              float* __restrict__ dst, int Pp) {
    int i = blockIdx.x * blockDim.x + threadIdx.x;
    if (i >= Pp) return;
    dst[i] = a[i]; dst[Pp + i] = b[i]; dst[2 * Pp + i] = c[i]; dst[3 * Pp + i] = d[i];
}

// ---------------- big SGEMM: C[N,P] = X[N,D] @ W[D,P] + bias ----------------
#define GBM 128
#define GBN 128
#define GBK 16
__global__ void __launch_bounds__(256)
gemm128_kernel(const float* __restrict__ X, const float* __restrict__ W,
               const float* __restrict__ bias, float* __restrict__ C,
               int D, int P) {
    __shared__ float As[GBK][GBM];
    __shared__ float Bs[GBK][GBN];
    int tid = threadIdx.x;
    int bm = blockIdx.x * GBM;
    int bn = blockIdx.y * GBN;

    int ar = tid >> 1;
    int ak = (tid & 1) << 3;
    int bk = tid >> 5;
    int bc = (tid & 31) << 2;
    int tr = tid >> 4, tc = tid & 15;

    const float* xr = X + (size_t)(bm + ar) * D + ak;
    float acc[8][8] = {};

    for (int k0 = 0; k0 < D; k0 += GBK) {
        float4 a0 = *(const float4*)(xr + k0);
        float4 a1 = *(const float4*)(xr + k0 + 4);
        As[ak + 0][ar] = a0.x; As[ak + 1][ar] = a0.y;
        As[ak + 2][ar] = a0.z; As[ak + 3][ar] = a0.w;
        As[ak + 4][ar] = a1.x; As[ak + 5][ar] = a1.y;
        As[ak + 6][ar] = a1.z; As[ak + 7][ar] = a1.w;
        *(float4*)&Bs[bk][bc] =
            *(const float4*)(W + (size_t)(k0 + bk) * P + bn + bc);
        *(float4*)&Bs[bk + 8][bc] =
            *(const float4*)(W + (size_t)(k0 + bk + 8) * P + bn + bc);
        __syncthreads();
#pragma unroll
        for (int kk = 0; kk < GBK; kk++) {
            float4 av0 = *(const float4*)&As[kk][tr * 8];
            float4 av1 = *(const float4*)&As[kk][tr * 8 + 4];
            float4 bv0 = *(const float4*)&Bs[kk][tc * 8];
            float4 bv1 = *(const float4*)&Bs[kk][tc * 8 + 4];
            float a[8] = {av0.x, av0.y, av0.z, av0.w, av1.x, av1.y, av1.z, av1.w};
            float bb[8] = {bv0.x, bv0.y, bv0.z, bv0.w, bv1.x, bv1.y, bv1.z, bv1.w};
#pragma unroll
            for (int i = 0; i < 8; i++)
#pragma unroll
                for (int j = 0; j < 8; j++)
                    acc[i][j] = fmaf(a[i], bb[j], acc[i][j]);
        }
        __syncthreads();
    }

    float bb0[8];
#pragma unroll
    for (int j = 0; j < 8; j++) bb0[j] = bias[bn + tc * 8 + j];
#pragma unroll
    for (int i = 0; i < 8; i++) {
        size_t row = bm + tr * 8 + i;
        float4 o0 = make_float4(acc[i][0] + bb0[0], acc[i][1] + bb0[1],
                                acc[i][2] + bb0[2], acc[i][3] + bb0[3]);
        float4 o1 = make_float4(acc[i][4] + bb0[4], acc[i][5] + bb0[5],
                                acc[i][6] + bb0[6], acc[i][7] + bb0[7]);
        *(float4*)(C + row * P + bn + tc * 8)     = o0;
        *(float4*)(C + row * P + bn + tc * 8 + 4) = o1;
    }
}

// ---------------- small SGEMM (layer 3, P=12), bounds-checked ----------------
#define BM 64
#define BN 64
#define BKT 16
__global__ void gemm_kernel(const float* __restrict__ X, const float* __restrict__ W,
                            const float* __restrict__ bias, float* __restrict__ C,
                            int D, int P) {
    __shared__ float As[BKT][BM];
    __shared__ float Bs[BKT][BN];
    int bm = blockIdx.x * BM;
    int bn = blockIdx.y * BN;
    int tid = threadIdx.x;
    int tr = tid >> 4, tc = tid & 15;
    float acc[4][4] = {};

    for (int k0 = 0; k0 < D; k0 += BKT) {
        for (int t = tid; t < BM * BKT; t += 256) {
            int m = t >> 4, k = t & 15;
            As[k][m] = X[(size_t)(bm + m) * D + k0 + k];
        }
        for (int t = tid; t < BKT * BN; t += 256) {
            int k = t >> 6, n = t & 63;
            int nn = bn + n;
            Bs[k][n] = (nn < P) ? W[(size_t)(k0 + k) * P + nn] : 0.f;
        }
        __syncthreads();
#pragma unroll
        for (int kk = 0; kk < BKT; kk++) {
            float4 av = *(const float4*)&As[kk][tr * 4];
            float4 bv = *(const float4*)&Bs[kk][tc * 4];
            float a[4] = {av.x, av.y, av.z, av.w};
            float bb[4] = {bv.x, bv.y, bv.z, bv.w};
#pragma unroll
            for (int i = 0; i < 4; i++)
#pragma unroll
                for (int j = 0; j < 4; j++)
                    acc[i][j] = fmaf(a[i], bb[j], acc[i][j]);
        }
        __syncthreads();
    }
#pragma unroll
    for (int i = 0; i < 4; i++) {
        int row = bm + tr * 4 + i;
#pragma unroll
        for (int j = 0; j < 4; j++) {
            int col = bn + tc * 4 + j;
            if (col < P) C[(size_t)row * P + col] = acc[i][j] + bias[col];
        }
    }
}

// ---------------- attention, c=128 layers (block per node); packed QKVS ----------------
__global__ void attn128_kernel(const float* __restrict__ pk,
                               const float* __restrict__ resid,
                               float* __restrict__ outp, int do_tanh) {
    __shared__ float sq[128];
    __shared__ float al[16];
    __shared__ int   nb[16];
    int i = blockIdx.x;
    int t = threadIdx.x;
    if (t < 16) nb[t] = g_nbr[i * 16 + t];
    sq[t] = pk[(size_t)i * 512 + t];            // Q at offset 0
    __syncthreads();

    int w = t >> 5, l = t & 31;
#pragma unroll
    for (int ee = 0; ee < 4; ee++) {
        int e = (w << 2) + ee;
        int j = nb[e];
        const float* kj = pk + (size_t)j * 512 + 128;   // K at offset 128
        float a = sq[l] * kj[l];
        a = fmaf(sq[l + 32], kj[l + 32], a);
        a = fmaf(sq[l + 64], kj[l + 64], a);
        a = fmaf(sq[l + 96], kj[l + 96], a);
#pragma unroll
        for (int o = 16; o > 0; o >>= 1) a += __shfl_xor_sync(0xffffffffu, a, o);
        if (l == 0) al[e] = a * 0.08838834764831845f;   // 1/sqrt(128)
    }
    __syncthreads();
    if (t < 32) {
        float a = (l < 16) ? al[l] : -__int_as_float(0x7f800000);
        float m = a;
#pragma unroll
        for (int o = 16; o > 0; o >>= 1) m = fmaxf(m, __shfl_xor_sync(0xffffffffu, m, o));
        float ex = (l < 16) ? expf(a - m) : 0.f;
        float sm = ex;
#pragma unroll
        for (int o = 16; o > 0; o >>= 1) sm += __shfl_xor_sync(0xffffffffu, sm, o);
        if (l < 16) al[l] = ex / sm;
    }
    __syncthreads();

    float acc = pk[(size_t)i * 512 + 384 + t];          // S at offset 384
#pragma unroll
    for (int e = 0; e < 16; e++)
        acc = fmaf(al[e], pk[(size_t)nb[e] * 512 + 256 + t], acc);  // V at 256
    if (resid) acc += resid[(size_t)i * 128 + t];
    outp[(size_t)i * 128 + t] = do_tanh ? tanhf(acc) : acc;
}

// ---------------- attention, c=3 final layer (warp per node); packed P=12 ----------------
__global__ void attn3_kernel(const float* __restrict__ pk, float* __restrict__ outp) {
    int gt = blockIdx.x * blockDim.x + threadIdx.x;
    int i = gt >> 5;
    int l = gt & 31;
    if (i >= NPTS) return;
    int j = 0;
    float a = -__int_as_float(0x7f800000);
    if (l < 16) {
        j = g_nbr[i * 16 + l];
        float qx = pk[i * 12 + 0], qy = pk[i * 12 + 1], qz = pk[i * 12 + 2];
        a = fmaf(qx, pk[j * 12 + 3], fmaf(qy, pk[j * 12 + 4], qz * pk[j * 12 + 5]))
            * 0.5773502691896258f;   // 1/sqrt(3)
    }
    float m = a;
#pragma unroll
    for (int o = 16; o > 0; o >>= 1) m = fmaxf(m, __shfl_xor_sync(0xffffffffu, m, o));
    float ex = (l < 16) ? expf(a - m) : 0.f;
    float sm = ex;
#pragma unroll
    for (int o = 16; o > 0; o >>= 1) sm += __shfl_xor_sync(0xffffffffu, sm, o);
    float wgt = ex / sm;
    float vx = 0.f, vy = 0.f, vz = 0.f;
    if (l < 16) {
        vx = wgt * pk[j * 12 + 6];
        vy = wgt * pk[j * 12 + 7];
        vz = wgt * pk[j * 12 + 8];
    }
#pragma unroll
    for (int o = 16; o > 0; o >>= 1) {
        vx += __shfl_xor_sync(0xffffffffu, vx, o);
        vy += __shfl_xor_sync(0xffffffffu, vy, o);
        vz += __shfl_xor_sync(0xffffffffu, vz, o);
    }
    if (l == 0) {
        outp[i * 3 + 0] = vx + pk[i * 12 + 9];
        outp[i * 3 + 1] = vy + pk[i * 12 + 10];
        outp[i * 3 + 2] = vz + pk[i * 12 + 11];
    }
}

// ---------------- host ----------------
extern "C" void kernel_launch(void* const* d_in, const int* in_sizes, int n_in,
                              void* d_out, int out_size) {
    const float* x = (const float*)d_in[1];
    const float* W1[4] = {(const float*)d_in[2], (const float*)d_in[4],
                          (const float*)d_in[6], (const float*)d_in[8]};
    const float* B1[4] = {(const float*)d_in[3], (const float*)d_in[5],
                          (const float*)d_in[7], (const float*)d_in[9]};
    const float* W2[4] = {(const float*)d_in[10], (const float*)d_in[12],
                          (const float*)d_in[14], (const float*)d_in[16]};
    const float* B2[4] = {(const float*)d_in[11], (const float*)d_in[13],
                          (const float*)d_in[15], (const float*)d_in[17]};
    const float* W3[4] = {(const float*)d_in[18], (const float*)d_in[20],
                          (const float*)d_in[22], (const float*)d_in[24]};
    const float* B3[4] = {(const float*)d_in[19], (const float*)d_in[21],
                          (const float*)d_in[23], (const float*)d_in[25]};
    float* out = (float*)d_out;

    float *qkvs, *h1, *h2, *Wp1, *Wp2, *Wp3, *Bp1, *Bp2, *Bp3;
    void *hist, *bbmin, *bbmax, *done;
    cudaGetSymbolAddress((void**)&qkvs, g_qkvs);
    cudaGetSymbolAddress((void**)&h1,  g_h1);
    cudaGetSymbolAddress((void**)&h2,  g_h2);
    cudaGetSymbolAddress((void**)&Wp1, g_Wp1);
    cudaGetSymbolAddress((void**)&Wp2, g_Wp2);
    cudaGetSymbolAddress((void**)&Wp3, g_Wp3);
    cudaGetSymbolAddress((void**)&Bp1, g_Bp1);
    cudaGetSymbolAddress((void**)&Bp2, g_Bp2);
    cudaGetSymbolAddress((void**)&Bp3, g_Bp3);
    cudaGetSymbolAddress(&hist,  g_hist);
    cudaGetSymbolAddress(&bbmin, g_bbmin);
    cudaGetSymbolAddress(&bbmax, g_bbmax);
    cudaGetSymbolAddress(&done,  g_done);

    // per-replay state reset (memset nodes, not kernel launches)
    cudaMemsetAsync(hist,  0x00, NCELLS * sizeof(int));
    cudaMemsetAsync(bbmin, 0xFF, 3 * sizeof(unsigned));
    cudaMemsetAsync(bbmax, 0x00, 3 * sizeof(unsigned));
    cudaMemsetAsync(done,  0x00, sizeof(unsigned));

    // slot 4 (ncu capture) = knn_query
    bbox_kernel<<<64, 256>>>(x);                                            // 1
    prep_hist_kernel<<<64, 256>>>(x);                                       // 2
    scan_scatter_kernel<<<1, 1024>>>();                                     // 3
    knn_query_kernel<<<NPTS / 8, 256>>>();                                  // 4 <- profiled

    pack_b_kernel<<<1, 128>>>(B1[0], B1[1], B1[2], B1[3], Bp1, 128);
    pack_b_kernel<<<1, 128>>>(B2[0], B2[1], B2[2], B2[3], Bp2, 128);
    pack_b_kernel<<<1, 128>>>(B3[0], B3[1], B3[2], B3[3], Bp3, 3);
    pack_w_kernel<<<(64 * 128 + 255) / 256, 256>>>(W1[0], W1[1], W1[2], W1[3], Wp1, 64, 128);
    pack_w_kernel<<<(128 * 128 + 255) / 256, 256>>>(W2[0], W2[1], W2[2], W2[3], Wp2, 128, 128);
    pack_w_kernel<<<(128 * 3 + 255) / 256, 256>>>(W3[0], W3[1], W3[2], W3[3], Wp3, 128, 3);

    // layer 1
    {
        dim3 grid(NPTS / GBM, 512 / GBN);
        gemm128_kernel<<<grid, 256>>>(x, Wp1, Bp1, qkvs, 64, 512);
    }
    attn128_kernel<<<NPTS, 128>>>(qkvs, nullptr, h1, 1);

    // layer 2
    {
        dim3 grid(NPTS / GBM, 512 / GBN);
        gemm128_kernel<<<grid, 256>>>(h1, Wp2, Bp2, qkvs, 128, 512);
    }
    attn128_kernel<<<NPTS, 128>>>(qkvs, h1, h2, 1);

    // layer 3
    {
        dim3 grid(NPTS / BM, 1);
        gemm_kernel<<<grid, 256>>>(h2, Wp3, Bp3, qkvs, 128, 12);
    }
    attn3_kernel<<<(NPTS * 32) / 128, 128>>>(qkvs, out);
}

// round 10
// speedup vs baseline: 1.6833x; 1.1059x over previous
#include <cuda_runtime.h>
#include <math.h>

#define NPTS 16384
#define KNN  16
#define LK   16          // per-lane list depth = KNN: provably exact
#define GD   32
#define NCELLS (GD * GD * GD)

// ---------------- scratch (device globals; no allocation allowed) ----------------
__device__ float4 g_pts [NPTS];
__device__ float4 g_spts[NPTS];
__device__ int    g_pcell[NPTS];
__device__ int    g_rank [NPTS];
__device__ int    g_ssid [NPTS];
__device__ int    g_scell[NPTS];
__device__ int    g_hist [NCELLS];
__device__ int    g_cellstart[NCELLS + 1];
__device__ unsigned g_bbminneg[3];   // running max of ~fkey(min)  -> zero-init valid
__device__ unsigned g_bbmaxk [3];    // running max of  fkey(max)  -> zero-init valid
__device__ unsigned g_done2;
__device__ unsigned g_ready;
__device__ float  g_gp[8];     // ox,oy,oz, ix,iy,iz, hmin, hdiag2
__device__ int    g_nbr [NPTS * KNN];
__device__ float  g_qkvs[NPTS * 512];
__device__ float  g_h1 [NPTS * 128];
__device__ float  g_h2 [NPTS * 128];
__device__ float  g_Wp1[64  * 512];
__device__ float  g_Wp2[128 * 512];
__device__ float  g_Wp3[128 * 12];
__device__ float  g_Bp1[512];
__device__ float  g_Bp2[512];
__device__ float  g_Bp3[12];

// monotone float <-> unsigned key
__device__ __forceinline__ unsigned fkey(float f) {
    unsigned u = __float_as_uint(f);
    return (u & 0x80000000u) ? ~u : (u | 0x80000000u);
}
__device__ __forceinline__ float funkey(unsigned u) {
    u = (u & 0x80000000u) ? (u & 0x7fffffffu) : ~u;
    return __uint_as_float(u);
}

// ---------------- fused bbox + grid-param + prep + hist (64 resident blocks) ----------------
__global__ void __launch_bounds__(256) bbox_prep_kernel(const float* __restrict__ x) {
    __shared__ float smn[3][8], smx[3][8];
    int tid = threadIdx.x;
    int i = blockIdx.x * 256 + tid;          // 64 blocks x 256 = 16384

    // zero hist slice BEFORE the barrier (2 cells per thread covers 32768)
    g_hist[i * 2] = 0;
    g_hist[i * 2 + 1] = 0;

    float v0 = x[i * 64 + 0], v1 = x[i * 64 + 1], v2 = x[i * 64 + 2];
    float mn[3] = {v0, v1, v2}, mx[3] = {v0, v1, v2};
#pragma unroll
    for (int o = 16; o > 0; o >>= 1)
#pragma unroll
        for (int d = 0; d < 3; d++) {
            mn[d] = fminf(mn[d], __shfl_xor_sync(0xffffffffu, mn[d], o));
            mx[d] = fmaxf(mx[d], __shfl_xor_sync(0xffffffffu, mx[d], o));
        }
    int w = tid >> 5, l = tid & 31;
    if (l == 0)
#pragma unroll
        for (int d = 0; d < 3; d++) { smn[d][w] = mn[d]; smx[d][w] = mx[d]; }
    __syncthreads();
    if (tid == 0) {
#pragma unroll
        for (int d = 0; d < 3; d++) {
            float a = smn[d][0], b = smx[d][0];
            for (int ww = 1; ww < 8; ww++) {
                a = fminf(a, smn[d][ww]); b = fmaxf(b, smx[d][ww]);
            }
            atomicMax(&g_bbminneg[d], ~fkey(a));
            atomicMax(&g_bbmaxk[d],  fkey(b));
        }
        __threadfence();
        if (atomicAdd(&g_done2, 1u) == 63u) {
            float hmin = 1e30f, hd2 = 0.f;
            for (int d = 0; d < 3; d++) {
                float lo = funkey(~atomicAdd(&g_bbminneg[d], 0u)) - 1e-4f;
                float hi = funkey(atomicAdd(&g_bbmaxk[d], 0u)) + 1e-4f;
                float h = (hi - lo) / (float)GD;
                g_gp[d] = lo;
                g_gp[3 + d] = (float)GD / (hi - lo);
                hmin = fminf(hmin, h);
                hd2 += h * h;
            }
            g_gp[6] = hmin;
            g_gp[7] = hd2;
            __threadfence();
            atomicExch(&g_ready, 1u);
        }
    }
    // all 64 blocks are resident: spin until grid params published
    if (tid == 0) { while (atomicAdd(&g_ready, 0u) == 0u) {} }
    __syncthreads();
    __threadfence();

    // prep + hist (after barrier, so hist zeroing is globally complete)
    g_pts[i] = make_float4(v0, v1, v2, v0 * v0 + v1 * v1 + v2 * v2);
    int cx = min(max((int)((v0 - g_gp[0]) * g_gp[3]), 0), GD - 1);
    int cy = min(max((int)((v1 - g_gp[1]) * g_gp[4]), 0), GD - 1);
    int cz = min(max((int)((v2 - g_gp[2]) * g_gp[5]), 0), GD - 1);
    int cell = (cz << 10) | (cy << 5) | cx;
    g_pcell[i] = cell;
    g_rank[i] = atomicAdd(&g_hist[cell], 1);
}

// ---------------- single-block scan; atomic-free direct-slot scatter ----------------
__global__ void __launch_bounds__(1024) scan_scatter_kernel() {
    __shared__ int sm[1024];
    int tid = threadIdx.x;
    int base = tid * (NCELLS / 1024);        // 32 cells per thread
    int s = 0;
    for (int j = 0; j < NCELLS / 1024; j++) s += g_hist[base + j];
    sm[tid] = s;
    __syncthreads();
    for (int off = 1; off < 1024; off <<= 1) {
        int v = (tid >= off) ? sm[tid - off] : 0;
        __syncthreads();
        sm[tid] += v;
        __syncthreads();
    }
    int run = sm[tid] - s;                   // exclusive
    for (int j = 0; j < NCELLS / 1024; j++) {
        g_cellstart[base + j] = run;
        run += g_hist[base + j];
    }
    if (tid == 1023) g_cellstart[NCELLS] = run;
    __syncthreads();
    for (int i = tid; i < NPTS; i += 1024) {
        int c = g_pcell[i];
        int slot = g_cellstart[c] + g_rank[i];
        g_spts[slot] = g_pts[i];
        g_ssid[slot] = i;
        g_scell[slot] = c;
    }
}

// stable ascending insert of (d, j) into LK-deep register list
__device__ __forceinline__ void insertL(float (&dist)[LK], int (&idx)[LK],
                                        float d, int j) {
#pragma unroll
    for (int s = LK - 1; s >= 0; --s) {
        float cur = dist[s];
        if (d < cur) {
            bool ins = (s == 0) || (d >= dist[s - 1]);
            dist[s] = ins ? d : dist[s - 1];
            idx [s] = ins ? j : idx [s - 1];
        }
    }
}

// warp-count points in clamped cube of Chebyshev radius R around (cx,cy,cz)
__device__ __forceinline__ int count_cube(int cx, int cy, int cz, int R, int lane) {
    int z0 = max(cz - R, 0), z1 = min(cz + R, GD - 1);
    int y0 = max(cy - R, 0), y1 = min(cy + R, GD - 1);
    int x0 = max(cx - R, 0), x1 = min(cx + R, GD - 1);
    int nyw = y1 - y0 + 1;
    int nrows = (z1 - z0 + 1) * nyw;
    int c = 0;
    for (int r = lane; r < nrows; r += 32) {
        int z = z0 + r / nyw, y = y0 + r % nyw;
        int rowb = (z << 10) | (y << 5);
        c += g_cellstart[rowb + x1 + 1] - g_cellstart[rowb + x0];
    }
#pragma unroll
    for (int o = 16; o > 0; o >>= 1) c += __shfl_xor_sync(0xffffffffu, c, o);
    return c;
}

// ---------------- exact kNN: warp/query, cheap bitonic bound + one culled scan ----------------
__global__ void __launch_bounds__(256) knn_query_kernel() {
    int t    = blockIdx.x * 8 + (threadIdx.x >> 5);   // one warp per sorted slot
    int lane = threadIdx.x & 31;
    float4 p = g_spts[t];
    int cc   = g_scell[t];
    int cx = cc & (GD - 1), cy = (cc >> 5) & (GD - 1), cz = cc >> 10;
    float nx = -2.f * p.x, ny = -2.f * p.y, nz = -2.f * p.z;
    int myid = g_ssid[t];

    // smallest cube with >= 17 points (incl. self)
    int R = 0;
    int cnt = g_cellstart[cc + 1] - g_cellstart[cc];
    while (cnt < KNN + 1 && R < GD) {
        R++;
        cnt = count_cube(cx, cy, cz, R, lane);
    }
    int z0a = max(cz - R, 0), z1a = min(cz + R, GD - 1);
    int y0a = max(cy - R, 0), y1a = min(cy + R, GD - 1);
    int x0a = max(cx - R, 0), x1a = min(cx + R, GD - 1);

    // ---- phase A: distance of each lane to one of the first 32 cube candidates
    //      (center row first so the subset is spatially near) ----
    float cv = __int_as_float(0x7f800000);
    int got = 0;
    {   // center row
        int rowb = (cz << 10) | (cy << 5);
        int s0 = g_cellstart[rowb + x0a], s1 = g_cellstart[rowb + x1a + 1];
        if (lane < s1 - s0) {
            float4 q = g_spts[s0 + lane];
            cv = fmaf(nx, q.x, fmaf(ny, q.y, fmaf(nz, q.z, q.w)));
        }
        got = s1 - s0;
    }
    for (int z = z0a; z <= z1a && got < 32; z++)
        for (int y = y0a; y <= y1a && got < 32; y++) {
            if (z == cz && y == cy) continue;
            int rowb = (z << 10) | (y << 5);
            int s0 = g_cellstart[rowb + x0a], s1 = g_cellstart[rowb + x1a + 1];
            int o = lane - got;
            if (o >= 0 && s0 + o < s1) {
                float4 q = g_spts[s0 + o];
                cv = fmaf(nx, q.x, fmaf(ny, q.y, fmaf(nz, q.z, q.w)));
            }
            got += s1 - s0;
        }
    // bitonic ascending sort of 32 lane values
#pragma unroll
    for (int k = 2; k <= 32; k <<= 1)
#pragma unroll
        for (int j = k >> 1; j > 0; j >>= 1) {
            float o = __shfl_xor_sync(0xffffffffu, cv, j);
            bool dirUp = ((lane & k) == 0);
            bool takeMin = (((lane & j) == 0) == dirUp);
            cv = takeMin ? fminf(cv, o) : fmaxf(cv, o);
        }
    float d17 = __shfl_sync(0xffffffffu, cv, 16);   // 17th smallest: >= true d16
    float kt  = fmaxf(d17 + p.w, 0.f) * 1.0002f + 1e-12f;   // true-squared bound
    float ktd = kt - p.w;                           // offset-space acceptance
    float rho = sqrtf(kt);
    float ixs = g_gp[3], iys = g_gp[4], izs = g_gp[5];
    int rx = (int)(rho * ixs) + 1;
    int ry = (int)(rho * iys) + 1;
    int rz = (int)(rho * izs) + 1;

    // ---- single scan of the kt-ball box, rows culled, x-range clamped ----
    float dist[LK];
    int   idx [LK];
#pragma unroll
    for (int u = 0; u < LK; u++) { dist[u] = __int_as_float(0x7f800000); idx[u] = 0x7fffffff; }

    float ox = g_gp[0], oy = g_gp[1], ozf = g_gp[2];
    float hy = 1.f / iys, hz = 1.f / izs;
    int bx0 = max(cx - rx, 0), bx1 = min(cx + rx, GD - 1);
    int by0 = max(cy - ry, 0), by1 = min(cy + ry, GD - 1);
    int bz0 = max(cz - rz, 0), bz1 = min(cz + rz, GD - 1);

    for (int z = bz0; z <= bz1; z++) {
        float zlo = fmaf((float)z, hz, ozf);
        float dzc = fmaxf(fmaxf(zlo - p.z, p.z - (zlo + hz)), 0.f);
        float dz2 = dzc * dzc;
        if (dz2 > kt) continue;
        for (int y = by0; y <= by1; y++) {
            float ylo = fmaf((float)y, hy, oy);
            float dyc = fmaxf(fmaxf(ylo - p.y, p.y - (ylo + hy)), 0.f);
            float rem = kt - fmaf(dyc, dyc, dz2);
            if (rem < 0.f) continue;
            float dxm = sqrtf(rem);
            int xlo = max(bx0, (int)((p.x - dxm - ox) * ixs));
            int xhi = min(bx1, (int)((p.x + dxm - ox) * ixs));
            if (xlo > xhi) continue;
            int rowb = (z << 10) | (y << 5);
            int s0 = g_cellstart[rowb + xlo];
            int s1 = g_cellstart[rowb + xhi + 1];
            for (int s = s0 + lane; s < s1; s += 32) {
                float4 q = g_spts[s];
                float d = fmaf(nx, q.x, fmaf(ny, q.y, fmaf(nz, q.z, q.w)));
                if (d < ktd && d < dist[LK - 1] && s != t) {
                    insertL(dist, idx, d, g_ssid[s]);
                }
            }
        }
    }

    // ---- merge 32 sorted lists: 16 rounds of warp-argmin on (fkey(d), id) ----
    unsigned out_id = 0;
#pragma unroll
    for (int u = 0; u < KNN; u++) {
        unsigned long long key =
            ((unsigned long long)fkey(dist[0]) << 32) | (unsigned)idx[0];
        unsigned long long m = key;
#pragma unroll
        for (int o = 16; o > 0; o >>= 1) {
            unsigned long long other = __shfl_xor_sync(0xffffffffu, m, o);
            m = (other < m) ? other : m;
        }
        if (key == m) {                  // winner pops its head
#pragma unroll
            for (int s2 = 0; s2 < LK - 1; s2++) {
                dist[s2] = dist[s2 + 1]; idx[s2] = idx[s2 + 1];
            }
            dist[LK - 1] = __int_as_float(0x7f800000);
            idx [LK - 1] = 0x7fffffff;
        }
        if (lane == u) out_id = (unsigned)(m & 0xffffffffu);
    }
    if (lane < KNN) g_nbr[myid * KNN + lane] = (int)out_id;
}

// ---------------- single fused weight/bias pack kernel ----------------
struct PackArgs {
    const float* w1[4]; const float* w2[4]; const float* w3[4];
    const float* b1[4]; const float* b2[4]; const float* b3[4];
};
__global__ void pack_all_kernel(PackArgs a) {
    int i = blockIdx.x * blockDim.x + threadIdx.x;
    if (i < 8192) {                                  // W1: 64x128 -> [64, 512]
        int r = i >> 7, col = i & 127;
        float* o = g_Wp1 + r * 512 + col;
        o[0] = a.w1[0][i]; o[128] = a.w1[1][i]; o[256] = a.w1[2][i]; o[384] = a.w1[3][i];
    } else if (i < 24576) {                          // W2: 128x128 -> [128, 512]
        int j = i - 8192;
        int r = j >> 7, col = j & 127;
        float* o = g_Wp2 + r * 512 + col;
        o[0] = a.w2[0][j]; o[128] = a.w2[1][j]; o[256] = a.w2[2][j]; o[384] = a.w2[3][j];
    } else if (i < 24960) {                          // W3: 128x3 -> [128, 12]
        int j = i - 24576;
        int r = j / 3, col = j - r * 3;
        float* o = g_Wp3 + r * 12 + col;
        o[0] = a.w3[0][j]; o[3] = a.w3[1][j]; o[6] = a.w3[2][j]; o[9] = a.w3[3][j];
    } else if (i < 25088) {                          // B1
        int j = i - 24960;
        g_Bp1[j] = a.b1[0][j]; g_Bp1[128 + j] = a.b1[1][j];
        g_Bp1[256 + j] = a.b1[2][j]; g_Bp1[384 + j] = a.b1[3][j];
    } else if (i < 25216) {                          // B2
        int j = i - 25088;
        g_Bp2[j] = a.b2[0][j]; g_Bp2[128 + j] = a.b2[1][j];
        g_Bp2[256 + j] = a.b2[2][j]; g_Bp2[384 + j] = a.b2[3][j];
    } else if (i < 25219) {                          // B3
        int j = i - 25216;
        g_Bp3[j] = a.b3[0][j]; g_Bp3[3 + j] = a.b3[1][j];
        g_Bp3[6 + j] = a.b3[2][j]; g_Bp3[9 + j] = a.b3[3][j];
    }
}

// ---------------- big SGEMM: C[N,P] = X[N,D] @ W[D,P] + bias ----------------
#define GBM 128
#define GBN 128
#define GBK 16
__global__ void __launch_bounds__(256)
gemm128_kernel(const float* __restrict__ X, const float* __restrict__ W,
               const float* __restrict__ bias, float* __restrict__ C,
               int D, int P) {
    __shared__ float As[GBK][GBM];
    __shared__ float Bs[GBK][GBN];
    int tid = threadIdx.x;
    int bm = blockIdx.x * GBM;
    int bn = blockIdx.y * GBN;

    int ar = tid >> 1;
    int ak = (tid & 1) << 3;
    int bk = tid >> 5;
    int bc = (tid & 31) << 2;
    int tr = tid >> 4, tc = tid & 15;

    const float* xr = X + (size_t)(bm + ar) * D + ak;
    float acc[8][8] = {};

    for (int k0 = 0; k0 < D; k0 += GBK) {
        float4 a0 = *(const float4*)(xr + k0);
        float4 a1 = *(const float4*)(xr + k0 + 4);
        As[ak + 0][ar] = a0.x; As[ak + 1][ar] = a0.y;
        As[ak + 2][ar] = a0.z; As[ak + 3][ar] = a0.w;
        As[ak + 4][ar] = a1.x; As[ak + 5][ar] = a1.y;
        As[ak + 6][ar] = a1.z; As[ak + 7][ar] = a1.w;
        *(float4*)&Bs[bk][bc] =
            *(const float4*)(W + (size_t)(k0 + bk) * P + bn + bc);
        *(float4*)&Bs[bk + 8][bc] =
            *(const float4*)(W + (size_t)(k0 + bk + 8) * P + bn + bc);
        __syncthreads();
#pragma unroll
        for (int kk = 0; kk < GBK; kk++) {
            float4 av0 = *(const float4*)&As[kk][tr * 8];
            float4 av1 = *(const float4*)&As[kk][tr * 8 + 4];
            float4 bv0 = *(const float4*)&Bs[kk][tc * 8];
            float4 bv1 = *(const float4*)&Bs[kk][tc * 8 + 4];
            float a[8] = {av0.x, av0.y, av0.z, av0.w, av1.x, av1.y, av1.z, av1.w};
            float bb[8] = {bv0.x, bv0.y, bv0.z, bv0.w, bv1.x, bv1.y, bv1.z, bv1.w};
#pragma unroll
            for (int i = 0; i < 8; i++)
#pragma unroll
                for (int j = 0; j < 8; j++)
                    acc[i][j] = fmaf(a[i], bb[j], acc[i][j]);
        }
        __syncthreads();
    }

    float bb0[8];
#pragma unroll
    for (int j = 0; j < 8; j++) bb0[j] = bias[bn + tc * 8 + j];
#pragma unroll
    for (int i = 0; i < 8; i++) {
        size_t row = bm + tr * 8 + i;
        float4 o0 = make_float4(acc[i][0] + bb0[0], acc[i][1] + bb0[1],
                                acc[i][2] + bb0[2], acc[i][3] + bb0[3]);
        float4 o1 = make_float4(acc[i][4] + bb0[4], acc[i][5] + bb0[5],
                                acc[i][6] + bb0[6], acc[i][7] + bb0[7]);
        *(float4*)(C + row * P + bn + tc * 8)     = o0;
        *(float4*)(C + row * P + bn + tc * 8 + 4) = o1;
    }
}

// ---------------- small SGEMM (layer 3, P=12), bounds-checked ----------------
#define BM 64
#define BN 64
#define BKT 16
__global__ void gemm_kernel(const float* __restrict__ X, const float* __restrict__ W,
                            const float* __restrict__ bias, float* __restrict__ C,
                            int D, int P) {
    __shared__ float As[BKT][BM];
    __shared__ float Bs[BKT][BN];
    int bm = blockIdx.x * BM;
    int bn = blockIdx.y * BN;
    int tid = threadIdx.x;
    int tr = tid >> 4, tc = tid & 15;
    float acc[4][4] = {};

    for (int k0 = 0; k0 < D; k0 += BKT) {
        for (int t = tid; t < BM * BKT; t += 256) {
            int m = t >> 4, k = t & 15;
            As[k][m] = X[(size_t)(bm + m) * D + k0 + k];
        }
        for (int t = tid; t < BKT * BN; t += 256) {
            int k = t >> 6, n = t & 63;
            int nn = bn + n;
            Bs[k][n] = (nn < P) ? W[(size_t)(k0 + k) * P + nn] : 0.f;
        }
        __syncthreads();
#pragma unroll
        for (int kk = 0; kk < BKT; kk++) {
            float4 av = *(const float4*)&As[kk][tr * 4];
            float4 bv = *(const float4*)&Bs[kk][tc * 4];
            float a[4] = {av.x, av.y, av.z, av.w};
            float bb[4] = {bv.x, bv.y, bv.z, bv.w};
#pragma unroll
            for (int i = 0; i < 4; i++)
#pragma unroll
                for (int j = 0; j < 4; j++)
                    acc[i][j] = fmaf(a[i], bb[j], acc[i][j]);
        }
        __syncthreads();
    }
#pragma unroll
    for (int i = 0; i < 4; i++) {
        int row = bm + tr * 4 + i;
#pragma unroll
        for (int j = 0; j < 4; j++) {
            int col = bn + tc * 4 + j;
            if (col < P) C[(size_t)row * P + col] = acc[i][j] + bias[col];
        }
    }
}

// ---------------- attention, c=128 layers (block per node); packed QKVS ----------------
__global__ void attn128_kernel(const float* __restrict__ pk,
                               const float* __restrict__ resid,
                               float* __restrict__ outp, int do_tanh) {
    __shared__ float sq[128];
    __shared__ float al[16];
    __shared__ int   nb[16];
    int i = blockIdx.x;
    int t = threadIdx.x;
    if (t < 16) nb[t] = g_nbr[i * 16 + t];
    sq[t] = pk[(size_t)i * 512 + t];            // Q at offset 0
    __syncthreads();

    int w = t >> 5, l = t & 31;
#pragma unroll
    for (int ee = 0; ee < 4; ee++) {
        int e = (w << 2) + ee;
        int j = nb[e];
        const float* kj = pk + (size_t)j * 512 + 128;   // K at offset 128
        float a = sq[l] * kj[l];
        a = fmaf(sq[l + 32], kj[l + 32], a);
        a = fmaf(sq[l + 64], kj[l + 64], a);
        a = fmaf(sq[l + 96], kj[l + 96], a);
#pragma unroll
        for (int o = 16; o > 0; o >>= 1) a += __shfl_xor_sync(0xffffffffu, a, o);
        if (l == 0) al[e] = a * 0.08838834764831845f;   // 1/sqrt(128)
    }
    __syncthreads();
    if (t < 32) {
        float a = (l < 16) ? al[l] : -__int_as_float(0x7f800000);
        float m = a;
#pragma unroll
        for (int o = 16; o > 0; o >>= 1) m = fmaxf(m, __shfl_xor_sync(0xffffffffu, m, o));
        float ex = (l < 16) ? expf(a - m) : 0.f;
        float sm = ex;
#pragma unroll
        for (int o = 16; o > 0; o >>= 1) sm += __shfl_xor_sync(0xffffffffu, sm, o);
        if (l < 16) al[l] = ex / sm;
    }
    __syncthreads();

    float acc = pk[(size_t)i * 512 + 384 + t];          // S at offset 384
#pragma unroll
    for (int e = 0; e < 16; e++)
        acc = fmaf(al[e], pk[(size_t)nb[e] * 512 + 256 + t], acc);  // V at 256
    if (resid) acc += resid[(size_t)i * 128 + t];
    outp[(size_t)i * 128 + t] = do_tanh ? tanhf(acc) : acc;
}

// ---------------- attention, c=3 final layer (warp per node); packed P=12 ----------------
// Also resets the bbox/barrier control words for the next graph replay.
__global__ void attn3_kernel(const float* __restrict__ pk, float* __restrict__ outp) {
    int gt = blockIdx.x * blockDim.x + threadIdx.x;
    if (gt == 0) {
        g_done2 = 0; g_ready = 0;
        g_bbminneg[0] = 0; g_bbminneg[1] = 0; g_bbminneg[2] = 0;
        g_bbmaxk[0] = 0;  g_bbmaxk[1] = 0;  g_bbmaxk[2] = 0;
    }
    int i = gt >> 5;
    int l = gt & 31;
    if (i >= NPTS) return;
    int j = 0;
    float a = -__int_as_float(0x7f800000);
    if (l < 16) {
        j = g_nbr[i * 16 + l];
        float qx = pk[i * 12 + 0], qy = pk[i * 12 + 1], qz = pk[i * 12 + 2];
        a = fmaf(qx, pk[j * 12 + 3], fmaf(qy, pk[j * 12 + 4], qz * pk[j * 12 + 5]))
            * 0.5773502691896258f;   // 1/sqrt(3)
    }
    float m = a;
#pragma unroll
    for (int o = 16; o > 0; o >>= 1) m = fmaxf(m, __shfl_xor_sync(0xffffffffu, m, o));
    float ex = (l < 16) ? expf(a - m) : 0.f;
    float sm = ex;
#pragma unroll
    for (int o = 16; o > 0; o >>= 1) sm += __shfl_xor_sync(0xffffffffu, sm, o);
    float wgt = ex / sm;
    float vx = 0.f, vy = 0.f, vz = 0.f;
    if (l < 16) {
        vx = wgt * pk[j * 12 + 6];
        vy = wgt * pk[j * 12 + 7];
        vz = wgt * pk[j * 12 + 8];
    }
#pragma unroll
    for (int o = 16; o > 0; o >>= 1) {
        vx += __shfl_xor_sync(0xffffffffu, vx, o);
        vy += __shfl_xor_sync(0xffffffffu, vy, o);
        vz += __shfl_xor_sync(0xffffffffu, vz, o);
    }
    if (l == 0) {
        outp[i * 3 + 0] = vx + pk[i * 12 + 9];
        outp[i * 3 + 1] = vy + pk[i * 12 + 10];
        outp[i * 3 + 2] = vz + pk[i * 12 + 11];
    }
}

// ---------------- host ----------------
extern "C" void kernel_launch(void* const* d_in, const int* in_sizes, int n_in,
                              void* d_out, int out_size) {
    const float* x = (const float*)d_in[1];
    PackArgs pa;
    for (int m = 0; m < 4; m++) {
        pa.w1[m] = (const float*)d_in[2 + 2 * m];
        pa.b1[m] = (const float*)d_in[3 + 2 * m];
        pa.w2[m] = (const float*)d_in[10 + 2 * m];
        pa.b2[m] = (const float*)d_in[11 + 2 * m];
        pa.w3[m] = (const float*)d_in[18 + 2 * m];
        pa.b3[m] = (const float*)d_in[19 + 2 * m];
    }
    float* out = (float*)d_out;

    float *qkvs, *h1, *h2, *Wp1, *Wp2, *Wp3, *Bp1, *Bp2, *Bp3;
    cudaGetSymbolAddress((void**)&qkvs, g_qkvs);
    cudaGetSymbolAddress((void**)&h1,  g_h1);
    cudaGetSymbolAddress((void**)&h2,  g_h2);
    cudaGetSymbolAddress((void**)&Wp1, g_Wp1);
    cudaGetSymbolAddress((void**)&Wp2, g_Wp2);
    cudaGetSymbolAddress((void**)&Wp3, g_Wp3);
    cudaGetSymbolAddress((void**)&Bp1, g_Bp1);
    cudaGetSymbolAddress((void**)&Bp2, g_Bp2);
    cudaGetSymbolAddress((void**)&Bp3, g_Bp3);

    // 10 kernel nodes, no memsets (state self-resets; zero-init valid on first run)
    bbox_prep_kernel<<<64, 256>>>(x);            // 1 (fused bbox+prep+hist)
    scan_scatter_kernel<<<1, 1024>>>();          // 2
    pack_all_kernel<<<99, 256>>>(pa);            // 3
    knn_query_kernel<<<NPTS / 8, 256>>>();       // 4 <- profiled

    // layer 1
    {
        dim3 grid(NPTS / GBM, 512 / GBN);
        gemm128_kernel<<<grid, 256>>>(x, Wp1, Bp1, qkvs, 64, 512);      // 5
    }
    attn128_kernel<<<NPTS, 128>>>(qkvs, nullptr, h1, 1);                // 6

    // layer 2
    {
        dim3 grid(NPTS / GBM, 512 / GBN);
        gemm128_kernel<<<grid, 256>>>(h1, Wp2, Bp2, qkvs, 128, 512);    // 7
    }
    attn128_kernel<<<NPTS, 128>>>(qkvs, h1, h2, 1);                     // 8

    // layer 3
    {
        dim3 grid(NPTS / BM, 1);
        gemm_kernel<<<grid, 256>>>(h2, Wp3, Bp3, qkvs, 128, 12);        // 9
    }
    attn3_kernel<<<(NPTS * 32) / 128, 128>>>(qkvs, out);                // 10
}

// round 11
// speedup vs baseline: 1.7268x; 1.0259x over previous
#include <cuda_runtime.h>
#include <math.h>

#define NPTS 16384
#define KNN  16
#define GD   32
#define NCELLS (GD * GD * GD)
#define CAP  64          // warp candidate buffer (overflow handled exactly)

// ---------------- scratch (device globals; no allocation allowed) ----------------
__device__ float4 g_pts [NPTS];
__device__ float4 g_spts[NPTS];
__device__ int    g_pcell[NPTS];
__device__ int    g_rank [NPTS];
__device__ int    g_ssid [NPTS];
__device__ int    g_scell[NPTS];
__device__ int    g_hist [NCELLS];
__device__ int    g_cellstart[NCELLS + 1];
__device__ unsigned g_bbminneg[3];   // running max of ~fkey(min)  -> zero-init valid
__device__ unsigned g_bbmaxk [3];    // running max of  fkey(max)  -> zero-init valid
__device__ unsigned g_done2;
__device__ unsigned g_ready;
__device__ float  g_gp[8];     // ox,oy,oz, ix,iy,iz, hmin, hdiag2
__device__ int    g_nbr [NPTS * KNN];
__device__ float  g_qkvs[NPTS * 512];
__device__ float  g_h1 [NPTS * 128];
__device__ float  g_h2 [NPTS * 128];
__device__ float  g_Wp1[64  * 512];
__device__ float  g_Wp2[128 * 512];
__device__ float  g_Wp3[128 * 12];
__device__ float  g_Bp1[512];
__device__ float  g_Bp2[512];
__device__ float  g_Bp3[12];

// monotone float <-> unsigned key
__device__ __forceinline__ unsigned fkey(float f) {
    unsigned u = __float_as_uint(f);
    return (u & 0x80000000u) ? ~u : (u | 0x80000000u);
}
__device__ __forceinline__ float funkey(unsigned u) {
    u = (u & 0x80000000u) ? (u & 0x7fffffffu) : ~u;
    return __uint_as_float(u);
}

// ---------------- fused bbox + grid-param + prep + hist (64 resident blocks) ----------------
__global__ void __launch_bounds__(256) bbox_prep_kernel(const float* __restrict__ x) {
    __shared__ float smn[3][8], smx[3][8];
    int tid = threadIdx.x;
    int i = blockIdx.x * 256 + tid;          // 64 blocks x 256 = 16384

    // zero hist slice BEFORE the barrier (2 cells per thread covers 32768)
    g_hist[i * 2] = 0;
    g_hist[i * 2 + 1] = 0;

    float v0 = x[i * 64 + 0], v1 = x[i * 64 + 1], v2 = x[i * 64 + 2];
    float mn[3] = {v0, v1, v2}, mx[3] = {v0, v1, v2};
#pragma unroll
    for (int o = 16; o > 0; o >>= 1)
#pragma unroll
        for (int d = 0; d < 3; d++) {
            mn[d] = fminf(mn[d], __shfl_xor_sync(0xffffffffu, mn[d], o));
            mx[d] = fmaxf(mx[d], __shfl_xor_sync(0xffffffffu, mx[d], o));
        }
    int w = tid >> 5, l = tid & 31;
    if (l == 0)
#pragma unroll
        for (int d = 0; d < 3; d++) { smn[d][w] = mn[d]; smx[d][w] = mx[d]; }
    __syncthreads();
    if (tid == 0) {
#pragma unroll
        for (int d = 0; d < 3; d++) {
            float a = smn[d][0], b = smx[d][0];
            for (int ww = 1; ww < 8; ww++) {
                a = fminf(a, smn[d][ww]); b = fmaxf(b, smx[d][ww]);
            }
            atomicMax(&g_bbminneg[d], ~fkey(a));
            atomicMax(&g_bbmaxk[d],  fkey(b));
        }
        __threadfence();
        if (atomicAdd(&g_done2, 1u) == 63u) {
            float hmin = 1e30f, hd2 = 0.f;
            for (int d = 0; d < 3; d++) {
                float lo = funkey(~atomicAdd(&g_bbminneg[d], 0u)) - 1e-4f;
                float hi = funkey(atomicAdd(&g_bbmaxk[d], 0u)) + 1e-4f;
                float h = (hi - lo) / (float)GD;
                g_gp[d] = lo;
                g_gp[3 + d] = (float)GD / (hi - lo);
                hmin = fminf(hmin, h);
                hd2 += h * h;
            }
            g_gp[6] = hmin;
            g_gp[7] = hd2;
            __threadfence();
            atomicExch(&g_ready, 1u);
        }
    }
    if (tid == 0) { while (atomicAdd(&g_ready, 0u) == 0u) {} }
    __syncthreads();
    __threadfence();

    g_pts[i] = make_float4(v0, v1, v2, v0 * v0 + v1 * v1 + v2 * v2);
    int cx = min(max((int)((v0 - g_gp[0]) * g_gp[3]), 0), GD - 1);
    int cy = min(max((int)((v1 - g_gp[1]) * g_gp[4]), 0), GD - 1);
    int cz = min(max((int)((v2 - g_gp[2]) * g_gp[5]), 0), GD - 1);
    int cell = (cz << 10) | (cy << 5) | cx;
    g_pcell[i] = cell;
    g_rank[i] = atomicAdd(&g_hist[cell], 1);
}

// ---------------- single-block scan; atomic-free direct-slot scatter ----------------
__global__ void __launch_bounds__(1024) scan_scatter_kernel() {
    __shared__ int sm[1024];
    int tid = threadIdx.x;
    int base = tid * (NCELLS / 1024);        // 32 cells per thread
    int s = 0;
    for (int j = 0; j < NCELLS / 1024; j++) s += g_hist[base + j];
    sm[tid] = s;
    __syncthreads();
    for (int off = 1; off < 1024; off <<= 1) {
        int v = (tid >= off) ? sm[tid - off] : 0;
        __syncthreads();
        sm[tid] += v;
        __syncthreads();
    }
    int run = sm[tid] - s;                   // exclusive
    for (int j = 0; j < NCELLS / 1024; j++) {
        g_cellstart[base + j] = run;
        run += g_hist[base + j];
    }
    if (tid == 1023) g_cellstart[NCELLS] = run;
    __syncthreads();
    for (int i = tid; i < NPTS; i += 1024) {
        int c = g_pcell[i];
        int slot = g_cellstart[c] + g_rank[i];
        g_spts[slot] = g_pts[i];
        g_ssid[slot] = i;
        g_scell[slot] = c;
    }
}

// warp-count points in clamped cube of Chebyshev radius R around (cx,cy,cz)
__device__ __forceinline__ int count_cube(int cx, int cy, int cz, int R, int lane) {
    int z0 = max(cz - R, 0), z1 = min(cz + R, GD - 1);
    int y0 = max(cy - R, 0), y1 = min(cy + R, GD - 1);
    int x0 = max(cx - R, 0), x1 = min(cx + R, GD - 1);
    int nyw = y1 - y0 + 1;
    int nrows = (z1 - z0 + 1) * nyw;
    int c = 0;
    for (int r = lane; r < nrows; r += 32) {
        int z = z0 + r / nyw, y = y0 + r % nyw;
        int rowb = (z << 10) | (y << 5);
        c += g_cellstart[rowb + x1 + 1] - g_cellstart[rowb + x0];
    }
#pragma unroll
    for (int o = 16; o > 0; o >>= 1) c += __shfl_xor_sync(0xffffffffu, c, o);
    return c;
}

// ---------------- exact kNN: warp/query, collect-then-bitonic-sort ----------------
__global__ void __launch_bounds__(256) knn_query_kernel() {
    const unsigned FULL = 0xffffffffu;
    __shared__ unsigned long long sbuf[8][CAP];
    int wslot = threadIdx.x >> 5;
    int t    = blockIdx.x * 8 + wslot;       // one warp per sorted slot
    int lane = threadIdx.x & 31;
    float4 p = g_spts[t];
    int cc   = g_scell[t];
    int cx = cc & (GD - 1), cy = (cc >> 5) & (GD - 1), cz = cc >> 10;
    float nx = -2.f * p.x, ny = -2.f * p.y, nz = -2.f * p.z;
    int myid = g_ssid[t];

    // smallest cube with >= 17 points (incl. self)
    int R = 0;
    int ccnt = g_cellstart[cc + 1] - g_cellstart[cc];
    while (ccnt < KNN + 1 && R < GD) {
        R++;
        ccnt = count_cube(cx, cy, cz, R, lane);
    }
    int z0a = max(cz - R, 0), z1a = min(cz + R, GD - 1);
    int y0a = max(cy - R, 0), y1a = min(cy + R, GD - 1);
    int x0a = max(cx - R, 0), x1a = min(cx + R, GD - 1);

    // ---- phase A: 17th smallest of first 32 cube candidates (center row first) ----
    float cv = __int_as_float(0x7f800000);
    int got = 0;
    {
        int rowb = (cz << 10) | (cy << 5);
        int s0 = g_cellstart[rowb + x0a], s1 = g_cellstart[rowb + x1a + 1];
        if (lane < s1 - s0) {
            float4 q = g_spts[s0 + lane];
            cv = fmaf(nx, q.x, fmaf(ny, q.y, fmaf(nz, q.z, q.w)));
        }
        got = s1 - s0;
    }
    for (int z = z0a; z <= z1a && got < 32; z++)
        for (int y = y0a; y <= y1a && got < 32; y++) {
            if (z == cz && y == cy) continue;
            int rowb = (z << 10) | (y << 5);
            int s0 = g_cellstart[rowb + x0a], s1 = g_cellstart[rowb + x1a + 1];
            int o = lane - got;
            if (o >= 0 && s0 + o < s1) {
                float4 q = g_spts[s0 + o];
                cv = fmaf(nx, q.x, fmaf(ny, q.y, fmaf(nz, q.z, q.w)));
            }
            got += s1 - s0;
        }
#pragma unroll
    for (int k = 2; k <= 32; k <<= 1)
#pragma unroll
        for (int j = k >> 1; j > 0; j >>= 1) {
            float o = __shfl_xor_sync(FULL, cv, j);
            bool dirUp = ((lane & k) == 0);
            bool takeMin = (((lane & j) == 0) == dirUp);
            cv = takeMin ? fminf(cv, o) : fmaxf(cv, o);
        }
    float d17 = __shfl_sync(FULL, cv, 16);   // >= true d16 (self is always rank 1)
    float kt  = fmaxf(d17 + p.w, 0.f) * 1.0002f + 1e-12f;   // true-squared bound

    float ixs = g_gp[3], iys = g_gp[4], izs = g_gp[5];
    float ox = g_gp[0], oy = g_gp[1], ozf = g_gp[2];
    float hy = 1.f / iys, hz = 1.f / izs;

    unsigned long long outk = ~0ull;
    for (int attempt = 0; attempt < 4; attempt++) {
        float ktd = kt - p.w;                // offset-space acceptance
        float rho = sqrtf(kt);
        int rx = (int)(rho * ixs) + 1;
        int ry = (int)(rho * iys) + 1;
        int rz = (int)(rho * izs) + 1;
        int bx0 = max(cx - rx, 0), bx1 = min(cx + rx, GD - 1);
        int by0 = max(cy - ry, 0), by1 = min(cy + ry, GD - 1);
        int bz0 = max(cz - rz, 0), bz1 = min(cz + rz, GD - 1);

        int cnt = 0;
        for (int z = bz0; z <= bz1; z++) {
            float zlo = fmaf((float)z, hz, ozf);
            float dzc = fmaxf(fmaxf(zlo - p.z, p.z - (zlo + hz)), 0.f);
            float dz2 = dzc * dzc;
            if (dz2 > kt) continue;
            for (int y = by0; y <= by1; y++) {
                float ylo = fmaf((float)y, hy, oy);
                float dyc = fmaxf(fmaxf(ylo - p.y, p.y - (ylo + hy)), 0.f);
                float rem = kt - fmaf(dyc, dyc, dz2);
                if (rem < 0.f) continue;
                float dxm = sqrtf(rem);
                int xlo = max(bx0, (int)((p.x - dxm - ox) * ixs));
                int xhi = min(bx1, (int)((p.x + dxm - ox) * ixs));
                if (xlo > xhi) continue;
                int rowb = (z << 10) | (y << 5);
                int s0 = g_cellstart[rowb + xlo];
                int s1 = g_cellstart[rowb + xhi + 1];
                for (int base = s0; base < s1; base += 32) {
                    int s = base + lane;
                    bool pass = false;
                    unsigned long long key = 0;
                    if (s < s1) {
                        float4 q = g_spts[s];
                        float d = fmaf(nx, q.x, fmaf(ny, q.y, fmaf(nz, q.z, q.w)));
                        if (d < ktd && s != t) {
                            pass = true;
                            key = ((unsigned long long)fkey(d) << 32) |
                                  (unsigned)g_ssid[s];
                        }
                    }
                    unsigned mask = __ballot_sync(FULL, pass);
                    int ofs = cnt + __popc(mask & ((1u << lane) - 1u));
                    if (pass && ofs < CAP) sbuf[wslot][ofs] = key;
                    cnt += __popc(mask);
                }
            }
        }

        // ---- bitonic sort of 64 u64 keys (2 regs/lane, v = r*32+lane) ----
        int lim = min(cnt, CAP);
        unsigned long long k0 = (lane      < lim) ? sbuf[wslot][lane]      : ~0ull;
        unsigned long long k1 = (lane + 32 < lim) ? sbuf[wslot][lane + 32] : ~0ull;
#pragma unroll
        for (int kk = 2; kk <= 64; kk <<= 1) {
#pragma unroll
            for (int j = kk >> 1; j > 0; j >>= 1) {
                if (j == 32) {   // register exchange (only when kk == 64, up=true)
                    unsigned long long lo = k0 < k1 ? k0 : k1;
                    unsigned long long hi = k0 < k1 ? k1 : k0;
                    k0 = lo; k1 = hi;
                } else {
                    bool up0 = (((0 * 32 + lane) & kk) == 0);
                    bool up1 = (((1 * 32 + lane) & kk) == 0);
                    unsigned long long o0 = __shfl_xor_sync(FULL, k0, j);
                    unsigned long long o1 = __shfl_xor_sync(FULL, k1, j);
                    bool tm0 = (((lane & j) == 0) == up0);
                    bool tm1 = (((lane & j) == 0) == up1);
                    k0 = tm0 ? (k0 < o0 ? k0 : o0) : (k0 > o0 ? k0 : o0);
                    k1 = tm1 ? (k1 < o1 ? k1 : o1) : (k1 > o1 ? k1 : o1);
                }
            }
        }
        outk = k0;                            // elements 0..31 live in k0
        if (cnt <= CAP) break;
        // overflow: 16th smallest of collected subset is a valid upper bound on d16
        unsigned long long k15 = __shfl_sync(FULL, k0, 15);
        float d16s = funkey((unsigned)(k15 >> 32));
        kt = fmaxf(d16s + p.w, 0.f) * 1.0002f + 1e-12f;
    }

    if (lane < KNN) g_nbr[myid * KNN + lane] = (int)(outk & 0xffffffffu);
}

// ---------------- single fused weight/bias pack kernel ----------------
struct PackArgs {
    const float* w1[4]; const float* w2[4]; const float* w3[4];
    const float* b1[4]; const float* b2[4]; const float* b3[4];
};
__global__ void pack_all_kernel(PackArgs a) {
    int i = blockIdx.x * blockDim.x + threadIdx.x;
    if (i < 8192) {                                  // W1: 64x128 -> [64, 512]
        int r = i >> 7, col = i & 127;
        float* o = g_Wp1 + r * 512 + col;
        o[0] = a.w1[0][i]; o[128] = a.w1[1][i]; o[256] = a.w1[2][i]; o[384] = a.w1[3][i];
    } else if (i < 24576) {                          // W2: 128x128 -> [128, 512]
        int j = i - 8192;
        int r = j >> 7, col = j & 127;
        float* o = g_Wp2 + r * 512 + col;
        o[0] = a.w2[0][j]; o[128] = a.w2[1][j]; o[256] = a.w2[2][j]; o[384] = a.w2[3][j];
    } else if (i < 24960) {                          // W3: 128x3 -> [128, 12]
        int j = i - 24576;
        int r = j / 3, col = j - r * 3;
        float* o = g_Wp3 + r * 12 + col;
        o[0] = a.w3[0][j]; o[3] = a.w3[1][j]; o[6] = a.w3[2][j]; o[9] = a.w3[3][j];
    } else if (i < 25088) {                          // B1
        int j = i - 24960;
        g_Bp1[j] = a.b1[0][j]; g_Bp1[128 + j] = a.b1[1][j];
        g_Bp1[256 + j] = a.b1[2][j]; g_Bp1[384 + j] = a.b1[3][j];
    } else if (i < 25216) {                          // B2
        int j = i - 25088;
        g_Bp2[j] = a.b2[0][j]; g_Bp2[128 + j] = a.b2[1][j];
        g_Bp2[256 + j] = a.b2[2][j]; g_Bp2[384 + j] = a.b2[3][j];
    } else if (i < 25219) {                          // B3
        int j = i - 25216;
        g_Bp3[j] = a.b3[0][j]; g_Bp3[3 + j] = a.b3[1][j];
        g_Bp3[6 + j] = a.b3[2][j]; g_Bp3[9 + j] = a.b3[3][j];
    }
}

// ---------------- big SGEMM: C[N,P] = X[N,D] @ W[D,P] + bias ----------------
#define GBM 128
#define GBN 128
#define GBK 16
__global__ void __launch_bounds__(256)
gemm128_kernel(const float* __restrict__ X, const float* __restrict__ W,
               const float* __restrict__ bias, float* __restrict__ C,
               int D, int P) {
    __shared__ float As[GBK][GBM];
    __shared__ float Bs[GBK][GBN];
    int tid = threadIdx.x;
    int bm = blockIdx.x * GBM;
    int bn = blockIdx.y * GBN;

    int ar = tid >> 1;
    int ak = (tid & 1) << 3;
    int bk = tid >> 5;
    int bc = (tid & 31) << 2;
    int tr = tid >> 4, tc = tid & 15;

    const float* xr = X + (size_t)(bm + ar) * D + ak;
    float acc[8][8] = {};

    for (int k0 = 0; k0 < D; k0 += GBK) {
        float4 a0 = *(const float4*)(xr + k0);
        float4 a1 = *(const float4*)(xr + k0 + 4);
        As[ak + 0][ar] = a0.x; As[ak + 1][ar] = a0.y;
        As[ak + 2][ar] = a0.z; As[ak + 3][ar] = a0.w;
        As[ak + 4][ar] = a1.x; As[ak + 5][ar] = a1.y;
        As[ak + 6][ar] = a1.z; As[ak + 7][ar] = a1.w;
        *(float4*)&Bs[bk][bc] =
            *(const float4*)(W + (size_t)(k0 + bk) * P + bn + bc);
        *(float4*)&Bs[bk + 8][bc] =
            *(const float4*)(W + (size_t)(k0 + bk + 8) * P + bn + bc);
        __syncthreads();
#pragma unroll
        for (int kk = 0; kk < GBK; kk++) {
            float4 av0 = *(const float4*)&As[kk][tr * 8];
            float4 av1 = *(const float4*)&As[kk][tr * 8 + 4];
            float4 bv0 = *(const float4*)&Bs[kk][tc * 8];
            float4 bv1 = *(const float4*)&Bs[kk][tc * 8 + 4];
            float a[8] = {av0.x, av0.y, av0.z, av0.w, av1.x, av1.y, av1.z, av1.w};
            float bb[8] = {bv0.x, bv0.y, bv0.z, bv0.w, bv1.x, bv1.y, bv1.z, bv1.w};
#pragma unroll
            for (int i = 0; i < 8; i++)
#pragma unroll
                for (int j = 0; j < 8; j++)
                    acc[i][j] = fmaf(a[i], bb[j], acc[i][j]);
        }
        __syncthreads();
    }

    float bb0[8];
#pragma unroll
    for (int j = 0; j < 8; j++) bb0[j] = bias[bn + tc * 8 + j];
#pragma unroll
    for (int i = 0; i < 8; i++) {
        size_t row = bm + tr * 8 + i;
        float4 o0 = make_float4(acc[i][0] + bb0[0], acc[i][1] + bb0[1],
                                acc[i][2] + bb0[2], acc[i][3] + bb0[3]);
        float4 o1 = make_float4(acc[i][4] + bb0[4], acc[i][5] + bb0[5],
                                acc[i][6] + bb0[6], acc[i][7] + bb0[7]);
        *(float4*)(C + row * P + bn + tc * 8)     = o0;
        *(float4*)(C + row * P + bn + tc * 8 + 4) = o1;
    }
}

// ---------------- small SGEMM (layer 3, P=12), bounds-checked ----------------
#define BM 64
#define BN 64
#define BKT 16
__global__ void gemm_kernel(const float* __restrict__ X, const float* __restrict__ W,
                            const float* __restrict__ bias, float* __restrict__ C,
                            int D, int P) {
    __shared__ float As[BKT][BM];
    __shared__ float Bs[BKT][BN];
    int bm = blockIdx.x * BM;
    int bn = blockIdx.y * BN;
    int tid = threadIdx.x;
    int tr = tid >> 4, tc = tid & 15;
    float acc[4][4] = {};

    for (int k0 = 0; k0 < D; k0 += BKT) {
        for (int t = tid; t < BM * BKT; t += 256) {
            int m = t >> 4, k = t & 15;
            As[k][m] = X[(size_t)(bm + m) * D + k0 + k];
        }
        for (int t = tid; t < BKT * BN; t += 256) {
            int k = t >> 6, n = t & 63;
            int nn = bn + n;
            Bs[k][n] = (nn < P) ? W[(size_t)(k0 + k) * P + nn] : 0.f;
        }
        __syncthreads();
#pragma unroll
        for (int kk = 0; kk < BKT; kk++) {
            float4 av = *(const float4*)&As[kk][tr * 4];
            float4 bv = *(const float4*)&Bs[kk][tc * 4];
            float a[4] = {av.x, av.y, av.z, av.w};
            float bb[4] = {bv.x, bv.y, bv.z, bv.w};
#pragma unroll
            for (int i = 0; i < 4; i++)
#pragma unroll
                for (int j = 0; j < 4; j++)
                    acc[i][j] = fmaf(a[i], bb[j], acc[i][j]);
        }
        __syncthreads();
    }
#pragma unroll
    for (int i = 0; i < 4; i++) {
        int row = bm + tr * 4 + i;
#pragma unroll
        for (int j = 0; j < 4; j++) {
            int col = bn + tc * 4 + j;
            if (col < P) C[(size_t)row * P + col] = acc[i][j] + bias[col];
        }
    }
}

// ---------------- attention, c=128 layers (block per node); packed QKVS ----------------
__global__ void attn128_kernel(const float* __restrict__ pk,
                               const float* __restrict__ resid,
                               float* __restrict__ outp, int do_tanh) {
    __shared__ float sq[128];
    __shared__ float al[16];
    __shared__ int   nb[16];
    int i = blockIdx.x;
    int t = threadIdx.x;
    if (t < 16) nb[t] = g_nbr[i * 16 + t];
    sq[t] = pk[(size_t)i * 512 + t];            // Q at offset 0
    __syncthreads();

    int w = t >> 5, l = t & 31;
#pragma unroll
    for (int ee = 0; ee < 4; ee++) {
        int e = (w << 2) + ee;
        int j = nb[e];
        const float* kj = pk + (size_t)j * 512 + 128;   // K at offset 128
        float a = sq[l] * kj[l];
        a = fmaf(sq[l + 32], kj[l + 32], a);
        a = fmaf(sq[l + 64], kj[l + 64], a);
        a = fmaf(sq[l + 96], kj[l + 96], a);
#pragma unroll
        for (int o = 16; o > 0; o >>= 1) a += __shfl_xor_sync(0xffffffffu, a, o);
        if (l == 0) al[e] = a * 0.08838834764831845f;   // 1/sqrt(128)
    }
    __syncthreads();
    if (t < 32) {
        float a = (l < 16) ? al[l] : -__int_as_float(0x7f800000);
        float m = a;
#pragma unroll
        for (int o = 16; o > 0; o >>= 1) m = fmaxf(m, __shfl_xor_sync(0xffffffffu, m, o));
        float ex = (l < 16) ? expf(a - m) : 0.f;
        float sm = ex;
#pragma unroll
        for (int o = 16; o > 0; o >>= 1) sm += __shfl_xor_sync(0xffffffffu, sm, o);
        if (l < 16) al[l] = ex / sm;
    }
    __syncthreads();

    float acc = pk[(size_t)i * 512 + 384 + t];          // S at offset 384
#pragma unroll
    for (int e = 0; e < 16; e++)
        acc = fmaf(al[e], pk[(size_t)nb[e] * 512 + 256 + t], acc);  // V at 256
    if (resid) acc += resid[(size_t)i * 128 + t];
    outp[(size_t)i * 128 + t] = do_tanh ? tanhf(acc) : acc;
}

// ---------------- attention, c=3 final layer (warp per node); packed P=12 ----------------
// Also resets the bbox/barrier control words for the next graph replay.
__global__ void attn3_kernel(const float* __restrict__ pk, float* __restrict__ outp) {
    int gt = blockIdx.x * blockDim.x + threadIdx.x;
    if (gt == 0) {
        g_done2 = 0; g_ready = 0;
        g_bbminneg[0] = 0; g_bbminneg[1] = 0; g_bbminneg[2] = 0;
        g_bbmaxk[0] = 0;  g_bbmaxk[1] = 0;  g_bbmaxk[2] = 0;
    }
    int i = gt >> 5;
    int l = gt & 31;
    if (i >= NPTS) return;
    int j = 0;
    float a = -__int_as_float(0x7f800000);
    if (l < 16) {
        j = g_nbr[i * 16 + l];
        float qx = pk[i * 12 + 0], qy = pk[i * 12 + 1], qz = pk[i * 12 + 2];
        a = fmaf(qx, pk[j * 12 + 3], fmaf(qy, pk[j * 12 + 4], qz * pk[j * 12 + 5]))
            * 0.5773502691896258f;   // 1/sqrt(3)
    }
    float m = a;
#pragma unroll
    for (int o = 16; o > 0; o >>= 1) m = fmaxf(m, __shfl_xor_sync(0xffffffffu, m, o));
    float ex = (l < 16) ? expf(a - m) : 0.f;
    float sm = ex;
#pragma unroll
    for (int o = 16; o > 0; o >>= 1) sm += __shfl_xor_sync(0xffffffffu, sm, o);
    float wgt = ex / sm;
    float vx = 0.f, vy = 0.f, vz = 0.f;
    if (l < 16) {
        vx = wgt * pk[j * 12 + 6];
        vy = wgt * pk[j * 12 + 7];
        vz = wgt * pk[j * 12 + 8];
    }
#pragma unroll
    for (int o = 16; o > 0; o >>= 1) {
        vx += __shfl_xor_sync(0xffffffffu, vx, o);
        vy += __shfl_xor_sync(0xffffffffu, vy, o);
        vz += __shfl_xor_sync(0xffffffffu, vz, o);
    }
    if (l == 0) {
        outp[i * 3 + 0] = vx + pk[i * 12 + 9];
        outp[i * 3 + 1] = vy + pk[i * 12 + 10];
        outp[i * 3 + 2] = vz + pk[i * 12 + 11];
    }
}

// ---------------- host ----------------
extern "C" void kernel_launch(void* const* d_in, const int* in_sizes, int n_in,
                              void* d_out, int out_size) {
    const float* x = (const float*)d_in[1];
    PackArgs pa;
    for (int m = 0; m < 4; m++) {
        pa.w1[m] = (const float*)d_in[2 + 2 * m];
        pa.b1[m] = (const float*)d_in[3 + 2 * m];
        pa.w2[m] = (const float*)d_in[10 + 2 * m];
        pa.b2[m] = (const float*)d_in[11 + 2 * m];
        pa.w3[m] = (const float*)d_in[18 + 2 * m];
        pa.b3[m] = (const float*)d_in[19 + 2 * m];
    }
    float* out = (float*)d_out;

    float *qkvs, *h1, *h2, *Wp1, *Wp2, *Wp3, *Bp1, *Bp2, *Bp3;
    cudaGetSymbolAddress((void**)&qkvs, g_qkvs);
    cudaGetSymbolAddress((void**)&h1,  g_h1);
    cudaGetSymbolAddress((void**)&h2,  g_h2);
    cudaGetSymbolAddress((void**)&Wp1, g_Wp1);
    cudaGetSymbolAddress((void**)&Wp2, g_Wp2);
    cudaGetSymbolAddress((void**)&Wp3, g_Wp3);
    cudaGetSymbolAddress((void**)&Bp1, g_Bp1);
    cudaGetSymbolAddress((void**)&Bp2, g_Bp2);
    cudaGetSymbolAddress((void**)&Bp3, g_Bp3);

    // 10 kernel nodes, no memsets (state self-resets; zero-init valid on first run)
    bbox_prep_kernel<<<64, 256>>>(x);            // 1 (fused bbox+prep+hist)
    scan_scatter_kernel<<<1, 1024>>>();          // 2
    pack_all_kernel<<<99, 256>>>(pa);            // 3
    knn_query_kernel<<<NPTS / 8, 256>>>();       // 4 <- profiled

    // layer 1
    {
        dim3 grid(NPTS / GBM, 512 / GBN);
        gemm128_kernel<<<grid, 256>>>(x, Wp1, Bp1, qkvs, 64, 512);      // 5
    }
    attn128_kernel<<<NPTS, 128>>>(qkvs, nullptr, h1, 1);                // 6

    // layer 2
    {
        dim3 grid(NPTS / GBM, 512 / GBN);
        gemm128_kernel<<<grid, 256>>>(h1, Wp2, Bp2, qkvs, 128, 512);    // 7
    }
    attn128_kernel<<<NPTS, 128>>>(qkvs, h1, h2, 1);                     // 8

    // layer 3
    {
        dim3 grid(NPTS / BM, 1);
        gemm_kernel<<<grid, 256>>>(h2, Wp3, Bp3, qkvs, 128, 12);        // 9
    }
    attn3_kernel<<<(NPTS * 32) / 128, 128>>>(qkvs, out);                // 10
}

// round 13
// speedup vs baseline: 1.9774x; 1.1451x over previous
#include <cuda_runtime.h>
#include <math.h>

#define NPTS 16384
#define KNN  16
#define GD   32
#define NCELLS (GD * GD * GD)
#define CAP  64          // warp candidate buffer (overflow handled exactly)

// ---------------- scratch (device globals; no allocation allowed) ----------------
__device__ float4 g_pts [NPTS];
__device__ float4 g_spts[NPTS];
__device__ int    g_pcell[NPTS];
__device__ int    g_rank [NPTS];
__device__ int    g_ssid [NPTS];
__device__ int    g_scell[NPTS];
__device__ int    g_hist [NCELLS];
__device__ int    g_cellstart[NCELLS + 1];
__device__ unsigned g_bbminneg[3];   // running max of ~fkey(min)  -> zero-init valid
__device__ unsigned g_bbmaxk [3];    // running max of  fkey(max)  -> zero-init valid
__device__ unsigned g_done2;
__device__ unsigned g_ready;
__device__ float  g_gp[8];     // ox,oy,oz, ix,iy,iz, hmin, hdiag2
__device__ int    g_nbr [NPTS * KNN];
__device__ float  g_qkvs[NPTS * 512];
__device__ float  g_h1 [NPTS * 128];
__device__ float  g_h2 [NPTS * 128];
__device__ float  g_Wp1[64  * 512];
__device__ float  g_Wp2[128 * 512];
__device__ float  g_Wp3[128 * 12];
__device__ float  g_Bp1[512];
__device__ float  g_Bp2[512];
__device__ float  g_Bp3[12];

// monotone float <-> unsigned key
__device__ __forceinline__ unsigned fkey(float f) {
    unsigned u = __float_as_uint(f);
    return (u & 0x80000000u) ? ~u : (u | 0x80000000u);
}
__device__ __forceinline__ float funkey(unsigned u) {
    u = (u & 0x80000000u) ? (u & 0x7fffffffu) : ~u;
    return __uint_as_float(u);
}

// ---------------- fused bbox + grid-param + prep + hist (64 resident blocks) ----------------
__global__ void __launch_bounds__(256) bbox_prep_kernel(const float* __restrict__ x) {
    __shared__ float smn[3][8], smx[3][8];
    int tid = threadIdx.x;
    int i = blockIdx.x * 256 + tid;          // 64 blocks x 256 = 16384

    g_hist[i * 2] = 0;
    g_hist[i * 2 + 1] = 0;

    float v0 = x[i * 64 + 0], v1 = x[i * 64 + 1], v2 = x[i * 64 + 2];
    float mn[3] = {v0, v1, v2}, mx[3] = {v0, v1, v2};
#pragma unroll
    for (int o = 16; o > 0; o >>= 1)
#pragma unroll
        for (int d = 0; d < 3; d++) {
            mn[d] = fminf(mn[d], __shfl_xor_sync(0xffffffffu, mn[d], o));
            mx[d] = fmaxf(mx[d], __shfl_xor_sync(0xffffffffu, mx[d], o));
        }
    int w = tid >> 5, l = tid & 31;
    if (l == 0)
#pragma unroll
        for (int d = 0; d < 3; d++) { smn[d][w] = mn[d]; smx[d][w] = mx[d]; }
    __syncthreads();
    if (tid == 0) {
#pragma unroll
        for (int d = 0; d < 3; d++) {
            float a = smn[d][0], b = smx[d][0];
            for (int ww = 1; ww < 8; ww++) {
                a = fminf(a, smn[d][ww]); b = fmaxf(b, smx[d][ww]);
            }
            atomicMax(&g_bbminneg[d], ~fkey(a));
            atomicMax(&g_bbmaxk[d],  fkey(b));
        }
        __threadfence();
        if (atomicAdd(&g_done2, 1u) == 63u) {
            float hmin = 1e30f, hd2 = 0.f;
            for (int d = 0; d < 3; d++) {
                float lo = funkey(~atomicAdd(&g_bbminneg[d], 0u)) - 1e-4f;
                float hi = funkey(atomicAdd(&g_bbmaxk[d], 0u)) + 1e-4f;
                float h = (hi - lo) / (float)GD;
                g_gp[d] = lo;
                g_gp[3 + d] = (float)GD / (hi - lo);
                hmin = fminf(hmin, h);
                hd2 += h * h;
            }
            g_gp[6] = hmin;
            g_gp[7] = hd2;
            __threadfence();
            atomicExch(&g_ready, 1u);
        }
    }
    if (tid == 0) { while (atomicAdd(&g_ready, 0u) == 0u) {} }
    __syncthreads();
    __threadfence();

    g_pts[i] = make_float4(v0, v1, v2, v0 * v0 + v1 * v1 + v2 * v2);
    int cx = min(max((int)((v0 - g_gp[0]) * g_gp[3]), 0), GD - 1);
    int cy = min(max((int)((v1 - g_gp[1]) * g_gp[4]), 0), GD - 1);
    int cz = min(max((int)((v2 - g_gp[2]) * g_gp[5]), 0), GD - 1);
    int cell = (cz << 10) | (cy << 5) | cx;
    g_pcell[i] = cell;
    g_rank[i] = atomicAdd(&g_hist[cell], 1);
}

// ---------------- single-block scan; atomic-free direct-slot scatter ----------------
__global__ void __launch_bounds__(1024) scan_scatter_kernel() {
    __shared__ int sm[1024];
    int tid = threadIdx.x;
    int base = tid * (NCELLS / 1024);        // 32 cells per thread
    int s = 0;
    for (int j = 0; j < NCELLS / 1024; j++) s += g_hist[base + j];
    sm[tid] = s;
    __syncthreads();
    for (int off = 1; off < 1024; off <<= 1) {
        int v = (tid >= off) ? sm[tid - off] : 0;
        __syncthreads();
        sm[tid] += v;
        __syncthreads();
    }
    int run = sm[tid] - s;                   // exclusive
    for (int j = 0; j < NCELLS / 1024; j++) {
        g_cellstart[base + j] = run;
        run += g_hist[base + j];
    }
    if (tid == 1023) g_cellstart[NCELLS] = run;
    __syncthreads();
    for (int i = tid; i < NPTS; i += 1024) {
        int c = g_pcell[i];
        int slot = g_cellstart[c] + g_rank[i];
        g_spts[slot] = g_pts[i];
        g_ssid[slot] = i;
        g_scell[slot] = c;
    }
}

// warp-count points in clamped cube of Chebyshev radius R around (cx,cy,cz)
__device__ __forceinline__ int count_cube(int cx, int cy, int cz, int R, int lane) {
    int z0 = max(cz - R, 0), z1 = min(cz + R, GD - 1);
    int y0 = max(cy - R, 0), y1 = min(cy + R, GD - 1);
    int x0 = max(cx - R, 0), x1 = min(cx + R, GD - 1);
    int nyw = y1 - y0 + 1;
    int nrows = (z1 - z0 + 1) * nyw;
    int c = 0;
    for (int r = lane; r < nrows; r += 32) {
        int z = z0 + r / nyw, y = y0 + r % nyw;
        int rowb = (z << 10) | (y << 5);
        c += g_cellstart[rowb + x1 + 1] - g_cellstart[rowb + x0];
    }
#pragma unroll
    for (int o = 16; o > 0; o >>= 1) c += __shfl_xor_sync(0xffffffffu, c, o);
    return c;
}

// ---------------- exact kNN: warp/query; center-first bound + lane-parallel scan ----------------
__global__ void __launch_bounds__(256) knn_query_kernel() {
    const unsigned FULL = 0xffffffffu;
    __shared__ unsigned long long sbuf[8][CAP];
    int wslot = threadIdx.x >> 5;
    int t    = blockIdx.x * 8 + wslot;       // one warp per sorted slot
    int lane = threadIdx.x & 31;
    float4 p = g_spts[t];
    int cc   = g_scell[t];
    int cx = cc & (GD - 1), cy = (cc >> 5) & (GD - 1), cz = cc >> 10;
    float nx = -2.f * p.x, ny = -2.f * p.y, nz = -2.f * p.z;
    int myid = g_ssid[t];

    // smallest cube with >= 17 points (incl. self)
    int R = 0;
    int ccnt = g_cellstart[cc + 1] - g_cellstart[cc];
    while (ccnt < KNN + 1 && R < GD) {
        R++;
        ccnt = count_cube(cx, cy, cz, R, lane);
    }
    int z0a = max(cz - R, 0), z1a = min(cz + R, GD - 1);
    int y0a = max(cy - R, 0), y1a = min(cy + R, GD - 1);
    int x0a = max(cx - R, 0), x1a = min(cx + R, GD - 1);

    // ---- phase A: 17th smallest of first 32 cube candidates, CENTER ROW FIRST
    //      (tight bound: own-cell/adjacent candidates; proven in r10/r11) ----
    float cv = __int_as_float(0x7f800000);
    int got = 0;
    {   // center row
        int rowb = (cz << 10) | (cy << 5);
        int s0 = g_cellstart[rowb + x0a], s1 = g_cellstart[rowb + x1a + 1];
        if (lane < s1 - s0) {
            float4 q = g_spts[s0 + lane];
            cv = fmaf(nx, q.x, fmaf(ny, q.y, fmaf(nz, q.z, q.w)));
        }
        got = s1 - s0;
    }
    for (int z = z0a; z <= z1a && got < 32; z++)
        for (int y = y0a; y <= y1a && got < 32; y++) {
            if (z == cz && y == cy) continue;
            int rowb = (z << 10) | (y << 5);
            int s0 = g_cellstart[rowb + x0a], s1 = g_cellstart[rowb + x1a + 1];
            int o = lane - got;
            if (o >= 0 && s0 + o < s1) {
                float4 q = g_spts[s0 + o];
                cv = fmaf(nx, q.x, fmaf(ny, q.y, fmaf(nz, q.z, q.w)));
            }
            got += s1 - s0;
        }
#pragma unroll
    for (int k = 2; k <= 32; k <<= 1)
#pragma unroll
        for (int j = k >> 1; j > 0; j >>= 1) {
            float o = __shfl_xor_sync(FULL, cv, j);
            bool dirUp = ((lane & k) == 0);
            bool takeMin = (((lane & j) == 0) == dirUp);
            cv = takeMin ? fminf(cv, o) : fmaxf(cv, o);
        }
    float d17 = __shfl_sync(FULL, cv, 16);   // >= true d16 (self is always rank 1)
    float kt  = fmaxf(d17 + p.w, 0.f) * 1.0002f + 1e-12f;   // true-squared bound

    float ixs = g_gp[3], iys = g_gp[4], izs = g_gp[5];
    float ox = g_gp[0], oy = g_gp[1], ozf = g_gp[2];
    float hy = 1.f / iys, hz = 1.f / izs;

    unsigned long long outk = ~0ull;
    for (int attempt = 0; attempt < 6; attempt++) {
        float ktd = kt - p.w;                // offset-space acceptance
        float rho = sqrtf(kt);
        int rx = (int)(rho * ixs) + 1;
        int ry = (int)(rho * iys) + 1;
        int rz = (int)(rho * izs) + 1;
        int bx0 = max(cx - rx, 0), bx1 = min(cx + rx, GD - 1);
        int by0 = max(cy - ry, 0), by1 = min(cy + ry, GD - 1);
        int bz0 = max(cz - rz, 0), bz1 = min(cz + rz, GD - 1);
        int nyw = by1 - by0 + 1;
        int nrows = (bz1 - bz0 + 1) * nyw;

        int cnt = 0;
        for (int rbase = 0; rbase < nrows; rbase += 32) {
            int r = rbase + lane;
            int a0 = 0, a1 = 0;
            if (r < nrows) {
                int z = bz0 + r / nyw, y = by0 + r % nyw;
                // row culling against kt (per-lane, parallel)
                float zlo = fmaf((float)z, hz, ozf);
                float dzc = fmaxf(fmaxf(zlo - p.z, p.z - (zlo + hz)), 0.f);
                float ylo = fmaf((float)y, hy, oy);
                float dyc = fmaxf(fmaxf(ylo - p.y, p.y - (ylo + hy)), 0.f);
                float rem = kt - fmaf(dyc, dyc, dzc * dzc);
                if (rem >= 0.f) {
                    float dxm = sqrtf(rem);
                    int xlo = max(bx0, (int)((p.x - dxm - ox) * ixs));
                    int xhi = min(bx1, (int)((p.x + dxm - ox) * ixs));
                    if (xlo <= xhi) {
                        int rowb = (z << 10) | (y << 5);
                        a0 = g_cellstart[rowb + xlo];
                        a1 = g_cellstart[rowb + xhi + 1];
                    }
                }
            }
            unsigned rmask = __ballot_sync(FULL, a1 > a0);
            while (rmask) {
                int src = __ffs(rmask) - 1; rmask &= rmask - 1;
                int s0 = __shfl_sync(FULL, a0, src);
                int s1 = __shfl_sync(FULL, a1, src);
                for (int base = s0; base < s1; base += 32) {
                    int s = base + lane;
                    bool pass = false;
                    unsigned long long key = 0;
                    if (s < s1) {
                        float4 q = g_spts[s];
                        float d = fmaf(nx, q.x, fmaf(ny, q.y, fmaf(nz, q.z, q.w)));
                        if (d < ktd && s != t) {
                            pass = true;
                            key = ((unsigned long long)fkey(d) << 32) |
                                  (unsigned)g_ssid[s];
                        }
                    }
                    unsigned mask = __ballot_sync(FULL, pass);
                    int ofs = cnt + __popc(mask & ((1u << lane) - 1u));
                    if (pass && ofs < CAP) sbuf[wslot][ofs] = key;
                    cnt += __popc(mask);
                }
            }
        }

        // ---- bitonic sort of 64 u64 keys (2 regs/lane) ----
        int lim = min(cnt, CAP);
        unsigned long long k0 = (lane      < lim) ? sbuf[wslot][lane]      : ~0ull;
        unsigned long long k1 = (lane + 32 < lim) ? sbuf[wslot][lane + 32] : ~0ull;
#pragma unroll
        for (int kk = 2; kk <= 64; kk <<= 1) {
#pragma unroll
            for (int j = kk >> 1; j > 0; j >>= 1) {
                if (j == 32) {   // register exchange (only when kk == 64, up=true)
                    unsigned long long lo = k0 < k1 ? k0 : k1;
                    unsigned long long hi = k0 < k1 ? k1 : k0;
                    k0 = lo; k1 = hi;
                } else {
                    bool up0 = (((0 * 32 + lane) & kk) == 0);
                    bool up1 = (((1 * 32 + lane) & kk) == 0);
                    unsigned long long o0 = __shfl_xor_sync(FULL, k0, j);
                    unsigned long long o1 = __shfl_xor_sync(FULL, k1, j);
                    bool tm0 = (((lane & j) == 0) == up0);
                    bool tm1 = (((lane & j) == 0) == up1);
                    k0 = tm0 ? (k0 < o0 ? k0 : o0) : (k0 > o0 ? k0 : o0);
                    k1 = tm1 ? (k1 < o1 ? k1 : o1) : (k1 > o1 ? k1 : o1);
                }
            }
        }
        outk = k0;                            // elements 0..31 live in k0
        if (cnt <= CAP) break;
        // overflow: 16th smallest of collected subset is a valid upper bound on d16
        unsigned long long k15 = __shfl_sync(FULL, k0, 15);
        float d16s = funkey((unsigned)(k15 >> 32));
        kt = fmaxf(d16s + p.w, 0.f) * 1.0002f + 1e-12f;
    }

    if (lane < KNN) g_nbr[myid * KNN + lane] = (int)(outk & 0xffffffffu);
}

// ---------------- single fused weight/bias pack kernel ----------------
struct PackArgs {
    const float* w1[4]; const float* w2[4]; const float* w3[4];
    const float* b1[4]; const float* b2[4]; const float* b3[4];
};
__global__ void pack_all_kernel(PackArgs a) {
    int i = blockIdx.x * blockDim.x + threadIdx.x;
    if (i < 8192) {                                  // W1: 64x128 -> [64, 512]
        int r = i >> 7, col = i & 127;
        float* o = g_Wp1 + r * 512 + col;
        o[0] = a.w1[0][i]; o[128] = a.w1[1][i]; o[256] = a.w1[2][i]; o[384] = a.w1[3][i];
    } else if (i < 24576) {                          // W2: 128x128 -> [128, 512]
        int j = i - 8192;
        int r = j >> 7, col = j & 127;
        float* o = g_Wp2 + r * 512 + col;
        o[0] = a.w2[0][j]; o[128] = a.w2[1][j]; o[256] = a.w2[2][j]; o[384] = a.w2[3][j];
    } else if (i < 24960) {                          // W3: 128x3 -> [128, 12]
        int j = i - 24576;
        int r = j / 3, col = j - r * 3;
        float* o = g_Wp3 + r * 12 + col;
        o[0] = a.w3[0][j]; o[3] = a.w3[1][j]; o[6] = a.w3[2][j]; o[9] = a.w3[3][j];
    } else if (i < 25088) {                          // B1
        int j = i - 24960;
        g_Bp1[j] = a.b1[0][j]; g_Bp1[128 + j] = a.b1[1][j];
        g_Bp1[256 + j] = a.b1[2][j]; g_Bp1[384 + j] = a.b1[3][j];
    } else if (i < 25216) {                          // B2
        int j = i - 25088;
        g_Bp2[j] = a.b2[0][j]; g_Bp2[128 + j] = a.b2[1][j];
        g_Bp2[256 + j] = a.b2[2][j]; g_Bp2[384 + j] = a.b2[3][j];
    } else if (i < 25219) {                          // B3
        int j = i - 25216;
        g_Bp3[j] = a.b3[0][j]; g_Bp3[3 + j] = a.b3[1][j];
        g_Bp3[6 + j] = a.b3[2][j]; g_Bp3[9 + j] = a.b3[3][j];
    }
}

// ---------------- big SGEMM: C[N,P] = X[N,D] @ W[D,P] + bias ----------------
#define GBM 128
#define GBN 128
#define GBK 16
__global__ void __launch_bounds__(256)
gemm128_kernel(const float* __restrict__ X, const float* __restrict__ W,
               const float* __restrict__ bias, float* __restrict__ C,
               int D, int P) {
    __shared__ float As[GBK][GBM];
    __shared__ float Bs[GBK][GBN];
    int tid = threadIdx.x;
    int bm = blockIdx.x * GBM;
    int bn = blockIdx.y * GBN;

    int ar = tid >> 1;
    int ak = (tid & 1) << 3;
    int bk = tid >> 5;
    int bc = (tid & 31) << 2;
    int tr = tid >> 4, tc = tid & 15;

    const float* xr = X + (size_t)(bm + ar) * D + ak;
    float acc[8][8] = {};

    for (int k0 = 0; k0 < D; k0 += GBK) {
        float4 a0 = *(const float4*)(xr + k0);
        float4 a1 = *(const float4*)(xr + k0 + 4);
        As[ak + 0][ar] = a0.x; As[ak + 1][ar] = a0.y;
        As[ak + 2][ar] = a0.z; As[ak + 3][ar] = a0.w;
        As[ak + 4][ar] = a1.x; As[ak + 5][ar] = a1.y;
        As[ak + 6][ar] = a1.z; As[ak + 7][ar] = a1.w;
        *(float4*)&Bs[bk][bc] =
            *(const float4*)(W + (size_t)(k0 + bk) * P + bn + bc);
        *(float4*)&Bs[bk + 8][bc] =
            *(const float4*)(W + (size_t)(k0 + bk + 8) * P + bn + bc);
        __syncthreads();
#pragma unroll
        for (int kk = 0; kk < GBK; kk++) {
            float4 av0 = *(const float4*)&As[kk][tr * 8];
            float4 av1 = *(const float4*)&As[kk][tr * 8 + 4];
            float4 bv0 = *(const float4*)&Bs[kk][tc * 8];
            float4 bv1 = *(const float4*)&Bs[kk][tc * 8 + 4];
            float a[8] = {av0.x, av0.y, av0.z, av0.w, av1.x, av1.y, av1.z, av1.w};
            float bb[8] = {bv0.x, bv0.y, bv0.z, bv0.w, bv1.x, bv1.y, bv1.z, bv1.w};
#pragma unroll
            for (int i = 0; i < 8; i++)
#pragma unroll
                for (int j = 0; j < 8; j++)
                    acc[i][j] = fmaf(a[i], bb[j], acc[i][j]);
        }
        __syncthreads();
    }

    float bb0[8];
#pragma unroll
    for (int j = 0; j < 8; j++) bb0[j] = bias[bn + tc * 8 + j];
#pragma unroll
    for (int i = 0; i < 8; i++) {
        size_t row = bm + tr * 8 + i;
        float4 o0 = make_float4(acc[i][0] + bb0[0], acc[i][1] + bb0[1],
                                acc[i][2] + bb0[2], acc[i][3] + bb0[3]);
        float4 o1 = make_float4(acc[i][4] + bb0[4], acc[i][5] + bb0[5],
                                acc[i][6] + bb0[6], acc[i][7] + bb0[7]);
        *(float4*)(C + row * P + bn + tc * 8)     = o0;
        *(float4*)(C + row * P + bn + tc * 8 + 4) = o1;
    }
}

// ---------------- small SGEMM (layer 3, P=12), bounds-checked ----------------
#define BM 64
#define BN 64
#define BKT 16
__global__ void gemm_kernel(const float* __restrict__ X, const float* __restrict__ W,
                            const float* __restrict__ bias, float* __restrict__ C,
                            int D, int P) {
    __shared__ float As[BKT][BM];
    __shared__ float Bs[BKT][BN];
    int bm = blockIdx.x * BM;
    int bn = blockIdx.y * BN;
    int tid = threadIdx.x;
    int tr = tid >> 4, tc = tid & 15;
    float acc[4][4] = {};

    for (int k0 = 0; k0 < D; k0 += BKT) {
        for (int t = tid; t < BM * BKT; t += 256) {
            int m = t >> 4, k = t & 15;
            As[k][m] = X[(size_t)(bm + m) * D + k0 + k];
        }
        for (int t = tid; t < BKT * BN; t += 256) {
            int k = t >> 6, n = t & 63;
            int nn = bn + n;
            Bs[k][n] = (nn < P) ? W[(size_t)(k0 + k) * P + nn] : 0.f;
        }
        __syncthreads();
#pragma unroll
        for (int kk = 0; kk < BKT; kk++) {
            float4 av = *(const float4*)&As[kk][tr * 4];
            float4 bv = *(const float4*)&Bs[kk][tc * 4];
            float a[4] = {av.x, av.y, av.z, av.w};
            float bb[4] = {bv.x, bv.y, bv.z, bv.w};
#pragma unroll
            for (int i = 0; i < 4; i++)
#pragma unroll
                for (int j = 0; j < 4; j++)
                    acc[i][j] = fmaf(a[i], bb[j], acc[i][j]);
        }
        __syncthreads();
    }
#pragma unroll
    for (int i = 0; i < 4; i++) {
        int row = bm + tr * 4 + i;
#pragma unroll
        for (int j = 0; j < 4; j++) {
            int col = bn + tc * 4 + j;
            if (col < P) C[(size_t)row * P + col] = acc[i][j] + bias[col];
        }
    }
}

// ---------------- attention, c=128 layers (block per node); packed QKVS ----------------
__global__ void attn128_kernel(const float* __restrict__ pk,
                               const float* __restrict__ resid,
                               float* __restrict__ outp, int do_tanh) {
    __shared__ float sq[128];
    __shared__ float al[16];
    __shared__ int   nb[16];
    int i = blockIdx.x;
    int t = threadIdx.x;
    if (t < 16) nb[t] = g_nbr[i * 16 + t];
    sq[t] = pk[(size_t)i * 512 + t];            // Q at offset 0
    __syncthreads();

    int w = t >> 5, l = t & 31;
#pragma unroll
    for (int ee = 0; ee < 4; ee++) {
        int e = (w << 2) + ee;
        int j = nb[e];
        const float* kj = pk + (size_t)j * 512 + 128;   // K at offset 128
        float a = sq[l] * kj[l];
        a = fmaf(sq[l + 32], kj[l + 32], a);
        a = fmaf(sq[l + 64], kj[l + 64], a);
        a = fmaf(sq[l + 96], kj[l + 96], a);
#pragma unroll
        for (int o = 16; o > 0; o >>= 1) a += __shfl_xor_sync(0xffffffffu, a, o);
        if (l == 0) al[e] = a * 0.08838834764831845f;   // 1/sqrt(128)
    }
    __syncthreads();
    if (t < 32) {
        float a = (l < 16) ? al[l] : -__int_as_float(0x7f800000);
        float m = a;
#pragma unroll
        for (int o = 16; o > 0; o >>= 1) m = fmaxf(m, __shfl_xor_sync(0xffffffffu, m, o));
        float ex = (l < 16) ? expf(a - m) : 0.f;
        float sm = ex;
#pragma unroll
        for (int o = 16; o > 0; o >>= 1) sm += __shfl_xor_sync(0xffffffffu, sm, o);
        if (l < 16) al[l] = ex / sm;
    }
    __syncthreads();

    float acc = pk[(size_t)i * 512 + 384 + t];          // S at offset 384
#pragma unroll
    for (int e = 0; e < 16; e++)
        acc = fmaf(al[e], pk[(size_t)nb[e] * 512 + 256 + t], acc);  // V at 256
    if (resid) acc += resid[(size_t)i * 128 + t];
    outp[(size_t)i * 128 + t] = do_tanh ? tanhf(acc) : acc;
}

// ---------------- attention, c=3 final layer (warp per node); packed P=12 ----------------
// Also resets the bbox/barrier control words for the next graph replay.
__global__ void attn3_kernel(const float* __restrict__ pk, float* __restrict__ outp) {
    int gt = blockIdx.x * blockDim.x + threadIdx.x;
    if (gt == 0) {
        g_done2 = 0; g_ready = 0;
        g_bbminneg[0] = 0; g_bbminneg[1] = 0; g_bbminneg[2] = 0;
        g_bbmaxk[0] = 0;  g_bbmaxk[1] = 0;  g_bbmaxk[2] = 0;
    }
    int i = gt >> 5;
    int l = gt & 31;
    if (i >= NPTS) return;
    int j = 0;
    float a = -__int_as_float(0x7f800000);
    if (l < 16) {
        j = g_nbr[i * 16 + l];
        float qx = pk[i * 12 + 0], qy = pk[i * 12 + 1], qz = pk[i * 12 + 2];
        a = fmaf(qx, pk[j * 12 + 3], fmaf(qy, pk[j * 12 + 4], qz * pk[j * 12 + 5]))
            * 0.5773502691896258f;   // 1/sqrt(3)
    }
    float m = a;
#pragma unroll
    for (int o = 16; o > 0; o >>= 1) m = fmaxf(m, __shfl_xor_sync(0xffffffffu, m, o));
    float ex = (l < 16) ? expf(a - m) : 0.f;
    float sm = ex;
#pragma unroll
    for (int o = 16; o > 0; o >>= 1) sm += __shfl_xor_sync(0xffffffffu, sm, o);
    float wgt = ex / sm;
    float vx = 0.f, vy = 0.f, vz = 0.f;
    if (l < 16) {
        vx = wgt * pk[j * 12 + 6];
        vy = wgt * pk[j * 12 + 7];
        vz = wgt * pk[j * 12 + 8];
    }
#pragma unroll
    for (int o = 16; o > 0; o >>= 1) {
        vx += __shfl_xor_sync(0xffffffffu, vx, o);
        vy += __shfl_xor_sync(0xffffffffu, vy, o);
        vz += __shfl_xor_sync(0xffffffffu, vz, o);
    }
    if (l == 0) {
        outp[i * 3 + 0] = vx + pk[i * 12 + 9];
        outp[i * 3 + 1] = vy + pk[i * 12 + 10];
        outp[i * 3 + 2] = vz + pk[i * 12 + 11];
    }
}

// ---------------- host ----------------
extern "C" void kernel_launch(void* const* d_in, const int* in_sizes, int n_in,
                              void* d_out, int out_size) {
    const float* x = (const float*)d_in[1];
    PackArgs pa;
    for (int m = 0; m < 4; m++) {
        pa.w1[m] = (const float*)d_in[2 + 2 * m];
        pa.b1[m] = (const float*)d_in[3 + 2 * m];
        pa.w2[m] = (const float*)d_in[10 + 2 * m];
        pa.b2[m] = (const float*)d_in[11 + 2 * m];
        pa.w3[m] = (const float*)d_in[18 + 2 * m];
        pa.b3[m] = (const float*)d_in[19 + 2 * m];
    }
    float* out = (float*)d_out;

    float *qkvs, *h1, *h2, *Wp1, *Wp2, *Wp3, *Bp1, *Bp2, *Bp3;
    cudaGetSymbolAddress((void**)&qkvs, g_qkvs);
    cudaGetSymbolAddress((void**)&h1,  g_h1);
    cudaGetSymbolAddress((void**)&h2,  g_h2);
    cudaGetSymbolAddress((void**)&Wp1, g_Wp1);
    cudaGetSymbolAddress((void**)&Wp2, g_Wp2);
    cudaGetSymbolAddress((void**)&Wp3, g_Wp3);
    cudaGetSymbolAddress((void**)&Bp1, g_Bp1);
    cudaGetSymbolAddress((void**)&Bp2, g_Bp2);
    cudaGetSymbolAddress((void**)&Bp3, g_Bp3);

    // 10 kernel nodes, no memsets (state self-resets; zero-init valid on first run)
    bbox_prep_kernel<<<64, 256>>>(x);            // 1 (fused bbox+prep+hist)
    scan_scatter_kernel<<<1, 1024>>>();          // 2
    pack_all_kernel<<<99, 256>>>(pa);            // 3
    knn_query_kernel<<<NPTS / 8, 256>>>();       // 4 <- profiled

    // layer 1
    {
        dim3 grid(NPTS / GBM, 512 / GBN);
        gemm128_kernel<<<grid, 256>>>(x, Wp1, Bp1, qkvs, 64, 512);      // 5
    }
    attn128_kernel<<<NPTS, 128>>>(qkvs, nullptr, h1, 1);                // 6

    // layer 2
    {
        dim3 grid(NPTS / GBM, 512 / GBN);
        gemm128_kernel<<<grid, 256>>>(h1, Wp2, Bp2, qkvs, 128, 512);    // 7
    }
    attn128_kernel<<<NPTS, 128>>>(qkvs, h1, h2, 1);                     // 8

    // layer 3
    {
        dim3 grid(NPTS / BM, 1);
        gemm_kernel<<<grid, 256>>>(h2, Wp3, Bp3, qkvs, 128, 12);        // 9
    }
    attn3_kernel<<<(NPTS * 32) / 128, 128>>>(qkvs, out);                // 10
}